// round 11
// baseline (speedup 1.0000x reference)
#include <cuda_runtime.h>
#include <cuda_bf16.h>
#include <cstdint>

typedef unsigned long long ull;
typedef unsigned int uint;

#define T_STEPS 512
#define BATCH   64
#define DIN     512
#define HID     1024
#define GATES   4096
#define NB      128          // persistent grid: 128 CTAs x 8 units = 1024
#define NTH     512          // 16 warps: mi = w&3 (16-row), ni = w>>2 (8-col)
#define UPC     8

// ---------------- scratch -----------------------------------------------------
__device__ float g_G0[(size_t)T_STEPS * BATCH * GATES];       // X@Wih0^T + biases
// weights in per-lane B-fragment order: [cta][mat 3][ni 4][kstep 64][lane 32]
// each entry uint4 = {b0h, b1h, b0l, b1l}
__device__ uint4 g_wf[(size_t)NB * 3 * 4 * 64 * 32];
// hidden states in A-fragment order: [parity][hi/lo][((mt*64+ks)*32+lane)*4+reg]
__device__ uint g_h0f[2][2][32768];
__device__ uint g_h1f[2][2][32768];
__device__ unsigned g_bar_cnt;
__device__ volatile unsigned g_bar_epoch;
__device__ unsigned g_done_cnt;

// ---------------- helpers -----------------------------------------------------
__device__ __forceinline__ void ffma2(ull &acc, ull a, ull b) {
    asm("fma.rn.f32x2 %0, %1, %2, %0;" : "+l"(acc) : "l"(a), "l"(b));
}
__device__ __forceinline__ float f2sum(ull v) {
    union { ull u; float2 f; } x; x.u = v; return x.f.x + x.f.y;
}
__device__ __forceinline__ float sigmoidf_(float x) { return 1.0f / (1.0f + expf(-x)); }

__device__ __forceinline__ void mma16816(float d[4], uint a0, uint a1, uint a2, uint a3,
                                         uint b0, uint b1) {
    asm volatile("mma.sync.aligned.m16n8k16.row.col.f32.bf16.bf16.f32 "
        "{%0,%1,%2,%3}, {%4,%5,%6,%7}, {%8,%9}, {%0,%1,%2,%3};"
        : "+f"(d[0]), "+f"(d[1]), "+f"(d[2]), "+f"(d[3])
        : "r"(a0), "r"(a1), "r"(a2), "r"(a3), "r"(b0), "r"(b1));
}

__device__ __forceinline__ void prefetchL2(const void* p) {
    asm volatile("prefetch.global.L2 [%0];" :: "l"(p));
}

__device__ __forceinline__ void grid_sync(unsigned &my_epoch) {
    __threadfence();
    __syncthreads();
    if (threadIdx.x == 0) {
        my_epoch++;
        if (atomicAdd(&g_bar_cnt, 1u) == (unsigned)NB - 1u) {
            g_bar_cnt = 0u;
            __threadfence();
            g_bar_epoch = my_epoch;
        } else {
            while (g_bar_epoch < my_epoch) { }
            __threadfence();
        }
    }
    __syncthreads();
}

__device__ __forceinline__ uint pack_bf2(__nv_bfloat16 lo16, __nv_bfloat16 hi16) {
    return (uint)__bfloat16_as_ushort(lo16) | ((uint)__bfloat16_as_ushort(hi16) << 16);
}

// ---------------- prep: weights -> B-fragment order, bf16 hi/lo ---------------
__global__ void __launch_bounds__(256) prep_w(
    const float* __restrict__ Whh0, const float* __restrict__ Wih1,
    const float* __restrict__ Whh1)
{
    uint idx = blockIdx.x * 256u + threadIdx.x;
    uint lane = idx & 31u;
    uint ks   = (idx >> 5) & 63u;
    uint ni   = (idx >> 11) & 3u;
    uint cm   = idx >> 13;
    uint mat  = cm % 3u, cta = cm / 3u;

    const float* W = (mat == 0) ? Whh0 : (mat == 1) ? Wih1 : Whh1;
    uint n  = ni * 8u + (lane >> 2);       // col within CTA's 32: n = lu*4 + g
    uint lu = n >> 2, g = n & 3u;
    const float* row = W + (size_t)(g * HID + cta * UPC + lu) * HID;
    uint k0 = ks * 16u + (lane & 3u) * 2u;

    float f0 = row[k0],     f1 = row[k0 + 1];
    float f2 = row[k0 + 8], f3 = row[k0 + 9];
    __nv_bfloat16 h0 = __float2bfloat16(f0), h1 = __float2bfloat16(f1);
    __nv_bfloat16 h2 = __float2bfloat16(f2), h3 = __float2bfloat16(f3);
    uint4 v;
    v.x = pack_bf2(h0, h1);
    v.y = pack_bf2(h2, h3);
    v.z = pack_bf2(__float2bfloat16(f0 - __bfloat162float(h0)),
                   __float2bfloat16(f1 - __bfloat162float(h1)));
    v.w = pack_bf2(__float2bfloat16(f2 - __bfloat162float(h2)),
                   __float2bfloat16(f3 - __bfloat162float(h3)));
    g_wf[idx] = v;
}

// ---------------- precompute G0 = X @ Wih0^T + b (unchanged, proven) ----------
__global__ void __launch_bounds__(256) gemm_g0(
    const float* __restrict__ X, const float* __restrict__ W,
    const float* __restrict__ bi, const float* __restrict__ bh)
{
    __shared__ ull As[64 * 16];
    __shared__ ull Bs[64 * 16];
    const int tid = threadIdx.x;
    const int tx = tid & 15, ty = tid >> 4;
    const int m0 = blockIdx.y * 64, n0 = blockIdx.x * 64;

    ull acc[4][4];
#pragma unroll
    for (int i = 0; i < 4; i++)
#pragma unroll
        for (int j = 0; j < 4; j++) acc[i][j] = 0ull;

    for (int kb = 0; kb < DIN; kb += 32) {
#pragma unroll
        for (int r = 0; r < 2; r++) {
            int idx = tid + 256 * r;
            int row = idx >> 3, c4 = idx & 7;
            int kk = c4 * 2, s = row & 15;
            ulonglong2 xa = *(const ulonglong2*)&X[(size_t)(m0 + row) * DIN + kb + c4 * 4];
            As[row * 16 + (kk ^ s)]       = xa.x;
            As[row * 16 + ((kk + 1) ^ s)] = xa.y;
            ulonglong2 wb = *(const ulonglong2*)&W[(size_t)(n0 + row) * DIN + kb + c4 * 4];
            Bs[row * 16 + (kk ^ s)]       = wb.x;
            Bs[row * 16 + ((kk + 1) ^ s)] = wb.y;
        }
        __syncthreads();
#pragma unroll
        for (int kk = 0; kk < 16; kk++) {
            ull a[4], b[4];
#pragma unroll
            for (int i = 0; i < 4; i++) { int row = ty * 4 + i; a[i] = As[row * 16 + (kk ^ (row & 15))]; }
#pragma unroll
            for (int j = 0; j < 4; j++) { int row = tx * 4 + j; b[j] = Bs[row * 16 + (kk ^ (row & 15))]; }
#pragma unroll
            for (int i = 0; i < 4; i++)
#pragma unroll
                for (int j = 0; j < 4; j++) ffma2(acc[i][j], a[i], b[j]);
        }
        __syncthreads();
    }

    float bias[4];
#pragma unroll
    for (int j = 0; j < 4; j++) bias[j] = bi[n0 + tx * 4 + j] + bh[n0 + tx * 4 + j];
#pragma unroll
    for (int i = 0; i < 4; i++) {
        float4 v;
        v.x = f2sum(acc[i][0]) + bias[0];
        v.y = f2sum(acc[i][1]) + bias[1];
        v.z = f2sum(acc[i][2]) + bias[2];
        v.w = f2sum(acc[i][3]) + bias[3];
        *(float4*)&g_G0[(size_t)(m0 + ty * 4 + i) * GATES + n0 + tx * 4] = v;
    }
}

// -------- fused k-loop: layer0 + lagged layer1 in ONE pass over h0 ------------
// L0: d0 = h0_prev @ Whh0        (3 chains)
// L1: d1 = h0_prev @ Wih1 + h1_prev2 @ Whh1   (6 chains)
// h0 A-fragments are loaded ONCE and reused for Whh0 and Wih1.
template<bool L0, bool L1>
__device__ __forceinline__ void kloop(
    const uint* __restrict__ h0h, const uint* __restrict__ h0l,
    const uint* __restrict__ h1h, const uint* __restrict__ h1l,
    const uint4* __restrict__ wf0, const uint4* __restrict__ wf1,
    const uint4* __restrict__ wf2,
    int mi, int lane, int rot, float d0[3][4], float d1[6][4])
{
    const uint4* a0h = (const uint4*)h0h + (size_t)mi * 64 * 32 + lane;
    const uint4* a0l = (const uint4*)h0l + (size_t)mi * 64 * 32 + lane;
    const uint4* a1h = (const uint4*)h1h + (size_t)mi * 64 * 32 + lane;
    const uint4* a1l = (const uint4*)h1l + (size_t)mi * 64 * 32 + lane;
#pragma unroll 2
    for (int i = 0; i < 64; i++) {
        int ks = (i + rot) & 63;
        int off = ks * 32;
        uint4 A0h = a0h[off];
        uint4 A0l = a0l[off];
        if (L0) {
            uint4 b0 = __ldg(&wf0[off + lane]);
            mma16816(d0[0], A0h.x, A0h.y, A0h.z, A0h.w, b0.x, b0.y);
            mma16816(d0[1], A0l.x, A0l.y, A0l.z, A0l.w, b0.x, b0.y);
            mma16816(d0[2], A0h.x, A0h.y, A0h.z, A0h.w, b0.z, b0.w);
        }
        if (L1) {
            uint4 b1 = __ldg(&wf1[off + lane]);
            uint4 A1h = a1h[off];
            uint4 A1l = a1l[off];
            uint4 b2 = __ldg(&wf2[off + lane]);
            mma16816(d1[0], A0h.x, A0h.y, A0h.z, A0h.w, b1.x, b1.y);
            mma16816(d1[1], A0l.x, A0l.y, A0l.z, A0l.w, b1.x, b1.y);
            mma16816(d1[2], A0h.x, A0h.y, A0h.z, A0h.w, b1.z, b1.w);
            mma16816(d1[3], A1h.x, A1h.y, A1h.z, A1h.w, b2.x, b2.y);
            mma16816(d1[4], A1l.x, A1l.y, A1l.z, A1l.w, b2.x, b2.y);
            mma16816(d1[5], A1h.x, A1h.y, A1h.z, A1h.w, b2.z, b2.w);
        }
    }
}

// epilogue helper: split h to bf16 hi/lo and write A-fragment slots
__device__ __forceinline__ void store_hfrag(uint* dst_hi, uint* dst_lo,
                                            const float hf[8], int b, int cta) {
    int kstep = cta >> 1, khalf = cta & 1;
    int row = b & 15, mt = b >> 4;
    int regb = ((row >= 8) ? 1 : 0) + (khalf ? 2 : 0);
    int base = (mt * 64 + kstep) * 32 + (row & 7) * 4;
#pragma unroll
    for (int s = 0; s < 4; s++) {
        float x = hf[2 * s], y = hf[2 * s + 1];
        __nv_bfloat16 xh = __float2bfloat16(x), yh = __float2bfloat16(y);
        int idx = (base + s) * 4 + regb;
        dst_hi[idx] = pack_bf2(xh, yh);
        dst_lo[idx] = pack_bf2(__float2bfloat16(x - __bfloat162float(xh)),
                               __float2bfloat16(y - __bfloat162float(yh)));
    }
}

// ---------------- persistent recurrent kernel ---------------------------------
__global__ void __launch_bounds__(NTH) lstm_persistent(
    const float* __restrict__ bi1, const float* __restrict__ bh1,
    float* __restrict__ out)
{
    __shared__ float ds0[64 * 33];         // layer0 D routing tile
    __shared__ float ds1[64 * 33];         // layer1 D routing tile

    const int tid  = threadIdx.x;
    const int lane = tid & 31;
    const int warp = tid >> 5;
    const int mi   = warp & 3;             // 16-row tile
    const int ni   = warp >> 2;            // 8-col tile
    const int cta  = blockIdx.x;
    const int u_start = cta * UPC;
    const int rot  = cta & 63;             // per-CTA k-rotation: de-camp L2 slices

    // zero h0f parity 0 and h1f parity 1 (the two buffers read before first write)
    {
        int i0 = cta * NTH + tid;          // 0..65535
        ((uint*)g_h0f)[i0]         = 0u;   // h0f[0][*][*]
        ((uint*)g_h1f)[65536 + i0] = 0u;   // h1f[1][*][*]
    }
    float c0r[8], c1r[8];
#pragma unroll
    for (int u = 0; u < 8; u++) { c0r[u] = 0.f; c1r[u] = 0.f; }
    float b1r[32];
    if (tid < 64) {
#pragma unroll
        for (int g = 0; g < 4; g++)
#pragma unroll
            for (int u = 0; u < 8; u++)
                b1r[g * 8 + u] = bi1[g * HID + u_start + u] + bh1[g * HID + u_start + u];
    }

    unsigned my_epoch = 0;
    grid_sync(my_epoch);

    const uint4* wf0 = g_wf + ((size_t)(cta * 3 + 0) * 4 + ni) * 2048;  // Whh0
    const uint4* wf1 = g_wf + ((size_t)(cta * 3 + 1) * 4 + ni) * 2048;  // Wih1
    const uint4* wf2 = g_wf + ((size_t)(cta * 3 + 2) * 4 + ni) * 2048;  // Whh1

    const int r0  = 16 * mi + (lane >> 2);
    const int cc0 = 8 * ni + (lane & 3) * 2;

    // 513 phases: phase ph computes layer0 step ph (ph<512) and layer1 step ph-1 (ph>=1)
    for (int ph = 0; ph <= T_STEPS; ph++) {
        const int p = ph & 1, q = p ^ 1;
        const bool L0 = (ph < T_STEPS), L1 = (ph >= 1);

        if (L0 && tid < 64) {              // L2-prefetch G0 slice for step ph
            const float* gp = g_G0 + ((size_t)ph * BATCH + tid) * GATES + u_start;
            prefetchL2(gp);
            prefetchL2(gp + HID);
            prefetchL2(gp + 2 * HID);
            prefetchL2(gp + 3 * HID);
        }

        float d0[3][4], d1[6][4];
#pragma unroll
        for (int c = 0; c < 3; c++)
#pragma unroll
            for (int r = 0; r < 4; r++) d0[c][r] = 0.f;
#pragma unroll
        for (int c = 0; c < 6; c++)
#pragma unroll
            for (int r = 0; r < 4; r++) d1[c][r] = 0.f;

        if (L0 && L1)
            kloop<true, true>(g_h0f[p][0], g_h0f[p][1], g_h1f[p][0], g_h1f[p][1],
                              wf0, wf1, wf2, mi, lane, rot, d0, d1);
        else if (L0)
            kloop<true, false>(g_h0f[p][0], g_h0f[p][1], g_h1f[p][0], g_h1f[p][1],
                               wf0, wf1, wf2, mi, lane, rot, d0, d1);
        else
            kloop<false, true>(g_h0f[p][0], g_h0f[p][1], g_h1f[p][0], g_h1f[p][1],
                               wf0, wf1, wf2, mi, lane, rot, d0, d1);

        if (L0) {
            ds0[r0 * 33 + cc0]           = d0[0][0] + d0[1][0] + d0[2][0];
            ds0[r0 * 33 + cc0 + 1]       = d0[0][1] + d0[1][1] + d0[2][1];
            ds0[(r0 + 8) * 33 + cc0]     = d0[0][2] + d0[1][2] + d0[2][2];
            ds0[(r0 + 8) * 33 + cc0 + 1] = d0[0][3] + d0[1][3] + d0[2][3];
        }
        if (L1) {
            ds1[r0 * 33 + cc0]           = d1[0][0] + d1[1][0] + d1[2][0] + d1[3][0] + d1[4][0] + d1[5][0];
            ds1[r0 * 33 + cc0 + 1]       = d1[0][1] + d1[1][1] + d1[2][1] + d1[3][1] + d1[4][1] + d1[5][1];
            ds1[(r0 + 8) * 33 + cc0]     = d1[0][2] + d1[1][2] + d1[2][2] + d1[3][2] + d1[4][2] + d1[5][2];
            ds1[(r0 + 8) * 33 + cc0 + 1] = d1[0][3] + d1[1][3] + d1[2][3] + d1[3][3] + d1[4][3] + d1[5][3];
        }
        __syncthreads();

        if (tid < 64) {
            const int b = tid;
            if (L0) {                       // layer0 epilogue, step t = ph
                const float* gp = g_G0 + ((size_t)ph * BATCH + b) * GATES + u_start;
                float hf[8];
#pragma unroll
                for (int u = 0; u < 8; u++) {
                    float gi = ds0[b * 33 + u * 4 + 0] + gp[u];
                    float gf = ds0[b * 33 + u * 4 + 1] + gp[HID + u];
                    float gg = ds0[b * 33 + u * 4 + 2] + gp[2 * HID + u];
                    float go = ds0[b * 33 + u * 4 + 3] + gp[3 * HID + u];
                    float c = sigmoidf_(gf) * c0r[u] + sigmoidf_(gi) * tanhf(gg);
                    c0r[u] = c;
                    hf[u] = sigmoidf_(go) * tanhf(c);
                }
                store_hfrag(g_h0f[q][0], g_h0f[q][1], hf, b, cta);
                if (ph == T_STEPS - 1) {
                    float* so = out + (size_t)T_STEPS * BATCH * HID;
#pragma unroll
                    for (int u = 0; u < 8; u++) {
                        so[b * HID + u_start + u]         = hf[u];
                        so[65536 + b * HID + u_start + u] = c0r[u];
                    }
                }
            }
            if (L1) {                       // layer1 epilogue, step t = ph-1
                const int t1 = ph - 1;
                float hf[8];
#pragma unroll
                for (int u = 0; u < 8; u++) {
                    float gi = ds1[b * 33 + u * 4 + 0] + b1r[u];
                    float gf = ds1[b * 33 + u * 4 + 1] + b1r[8 + u];
                    float gg = ds1[b * 33 + u * 4 + 2] + b1r[16 + u];
                    float go = ds1[b * 33 + u * 4 + 3] + b1r[24 + u];
                    float c = sigmoidf_(gf) * c1r[u] + sigmoidf_(gi) * tanhf(gg);
                    c1r[u] = c;
                    hf[u] = sigmoidf_(go) * tanhf(c);
                }
                store_hfrag(g_h1f[q][0], g_h1f[q][1], hf, b, cta);
                float* orow = out + ((size_t)t1 * BATCH + b) * HID + u_start;
                *(float4*)&orow[0] = make_float4(hf[0], hf[1], hf[2], hf[3]);
                *(float4*)&orow[4] = make_float4(hf[4], hf[5], hf[6], hf[7]);
                if (ph == T_STEPS) {
                    float* so = out + (size_t)T_STEPS * BATCH * HID;
#pragma unroll
                    for (int u = 0; u < 8; u++) {
                        so[131072 + b * HID + u_start + u] = hf[u];
                        so[196608 + b * HID + u_start + u] = c1r[u];
                    }
                }
            }
        }
        grid_sync(my_epoch);
    }

    // ---- reset barrier vars for deterministic graph replay ----
    __threadfence();
    __syncthreads();
    if (tid == 0) {
        if (atomicAdd(&g_done_cnt, 1u) == (unsigned)NB - 1u) {
            g_done_cnt = 0u;
            g_bar_cnt  = 0u;
            __threadfence();
            g_bar_epoch = 0u;
        }
    }
}

// ---------------- launch ------------------------------------------------------
extern "C" void kernel_launch(void* const* d_in, const int* in_sizes, int n_in,
                              void* d_out, int out_size) {
    const float* X     = (const float*)d_in[0];
    const float* Wih0  = (const float*)d_in[1];
    const float* Whh0  = (const float*)d_in[2];
    const float* bih0  = (const float*)d_in[3];
    const float* bhh0  = (const float*)d_in[4];
    const float* Wih1  = (const float*)d_in[5];
    const float* Whh1  = (const float*)d_in[6];
    const float* bih1  = (const float*)d_in[7];
    const float* bhh1  = (const float*)d_in[8];
    float* out = (float*)d_out;

    prep_w<<<12288, 256>>>(Whh0, Wih1, Whh1);

    dim3 ggrid(GATES / 64, (T_STEPS * BATCH) / 64);
    gemm_g0<<<ggrid, 256>>>(X, Wih0, bih0, bhh0);

    lstm_persistent<<<NB, NTH>>>(bih1, bhh1, out);
}

// round 12
// speedup vs baseline: 1.4727x; 1.4727x over previous
#include <cuda_runtime.h>
#include <cuda_bf16.h>
#include <cstdint>

typedef unsigned long long ull;
typedef unsigned int uint;

#define T_STEPS 512
#define BATCH   64
#define DIN     512
#define HID     1024
#define GATES   4096
#define NB      128          // persistent grid: 128 CTAs x 8 units = 1024
#define NTH     512          // 16 warps: mi = w&3 (16-row), ni = w>>2 (8-col)
#define UPC     8

// ---------------- scratch -----------------------------------------------------
__device__ float g_G0[(size_t)T_STEPS * BATCH * GATES];       // X@Wih0^T + biases
// weights in per-lane B-fragment order: [cta][mat 3][ni 4][kstep 64][lane 32]
// each entry uint4 = {b0h, b1h, b0l, b1l}
__device__ uint4 g_wf[(size_t)NB * 3 * 4 * 64 * 32];
// hidden states in A-fragment order: [parity][hi/lo][((mt*64+ks)*32+lane)*4+reg]
__device__ uint g_h0f[2][2][32768];
__device__ uint g_h1f[2][2][32768];
__device__ unsigned g_bar_cnt;
__device__ volatile unsigned g_bar_epoch;
__device__ unsigned g_done_cnt;

// ---------------- helpers -----------------------------------------------------
__device__ __forceinline__ float sigmoidf_(float x) { return 1.0f / (1.0f + expf(-x)); }

__device__ __forceinline__ void mma16816(float d[4], uint a0, uint a1, uint a2, uint a3,
                                         uint b0, uint b1) {
    asm volatile("mma.sync.aligned.m16n8k16.row.col.f32.bf16.bf16.f32 "
        "{%0,%1,%2,%3}, {%4,%5,%6,%7}, {%8,%9}, {%0,%1,%2,%3};"
        : "+f"(d[0]), "+f"(d[1]), "+f"(d[2]), "+f"(d[3])
        : "r"(a0), "r"(a1), "r"(a2), "r"(a3), "r"(b0), "r"(b1));
}

__device__ __forceinline__ void prefetchL2(const void* p) {
    asm volatile("prefetch.global.L2 [%0];" :: "l"(p));
}

__device__ __forceinline__ void grid_sync(unsigned &my_epoch) {
    __threadfence();
    __syncthreads();
    if (threadIdx.x == 0) {
        my_epoch++;
        if (atomicAdd(&g_bar_cnt, 1u) == (unsigned)NB - 1u) {
            g_bar_cnt = 0u;
            __threadfence();
            g_bar_epoch = my_epoch;
        } else {
            while (g_bar_epoch < my_epoch) { }
            __threadfence();
        }
    }
    __syncthreads();
}

__device__ __forceinline__ uint pack_bf2(__nv_bfloat16 lo16, __nv_bfloat16 hi16) {
    return (uint)__bfloat16_as_ushort(lo16) | ((uint)__bfloat16_as_ushort(hi16) << 16);
}
// split two floats into bf16-hi pair and bf16-lo pair
__device__ __forceinline__ void split2(float x, float y, uint &hi, uint &lo) {
    __nv_bfloat16 xh = __float2bfloat16(x), yh = __float2bfloat16(y);
    hi = pack_bf2(xh, yh);
    lo = pack_bf2(__float2bfloat16(x - __bfloat162float(xh)),
                  __float2bfloat16(y - __bfloat162float(yh)));
}

// ---------------- prep: weights -> B-fragment order, bf16 hi/lo ---------------
__global__ void __launch_bounds__(256) prep_w(
    const float* __restrict__ Whh0, const float* __restrict__ Wih1,
    const float* __restrict__ Whh1)
{
    uint idx = blockIdx.x * 256u + threadIdx.x;
    uint lane = idx & 31u;
    uint ks   = (idx >> 5) & 63u;
    uint ni   = (idx >> 11) & 3u;
    uint cm   = idx >> 13;
    uint mat  = cm % 3u, cta = cm / 3u;

    const float* W = (mat == 0) ? Whh0 : (mat == 1) ? Wih1 : Whh1;
    uint n  = ni * 8u + (lane >> 2);       // col within CTA's 32: n = lu*4 + g
    uint lu = n >> 2, g = n & 3u;
    const float* row = W + (size_t)(g * HID + cta * UPC + lu) * HID;
    uint k0 = ks * 16u + (lane & 3u) * 2u;

    float f0 = row[k0],     f1 = row[k0 + 1];
    float f2 = row[k0 + 8], f3 = row[k0 + 9];
    uint4 v;
    split2(f0, f1, v.x, v.z);
    split2(f2, f3, v.y, v.w);
    g_wf[idx] = v;
}

// ---------------- tensorized G0 GEMM: G0 = X @ Wih0^T + b ---------------------
// CTA tile 128x128, K=512 in 32 slices of 16, double-buffered SMEM holding
// fragments directly in per-lane mma order. 512 threads = 16 warps, each warp
// 32x32 (2 m16 tiles x 4 n8 tiles), 3-term split-bf16.
__global__ void __launch_bounds__(512) gemm_g0_bf16(
    const float* __restrict__ X, const float* __restrict__ W,
    const float* __restrict__ bi, const float* __restrict__ bh)
{
    // [buf][plane hi/lo][mtile 8][lane 32][reg 4]
    __shared__ uint As[2][2][8][32][4];
    // [buf][plane hi/lo][ntile 16][lane 32][reg 2]
    __shared__ uint Bs[2][2][16][32][2];

    const int tid  = threadIdx.x;
    const int lane = tid & 31;
    const int warp = tid >> 5;
    const int wm   = warp >> 2;            // 0..3 : rows 32*wm
    const int wn   = warp & 3;             // 0..3 : cols 32*wn
    const int m0 = blockIdx.y * 128, n0 = blockIdx.x * 128;

    // per-thread load coords (one float4 of X and one of W per slice)
    const int lrow = tid >> 2;             // 0..127
    const int c0   = (tid & 3) * 4;        // k offset 0,4,8,12
    const int j0   = c0 >> 1;              // k-pair 0,2,4,6
    // A-fragment store slots
    const int a_mt  = lrow >> 4, a_rr = lrow & 15;
    const int a_reg = (a_rr >= 8 ? 1 : 0) + (j0 >= 4 ? 2 : 0);
    const int a_ln  = (a_rr & 7) * 4 + (j0 & 3);
    // B-fragment store slots
    const int b_nt  = lrow >> 3, b_nn = lrow & 7;
    const int b_reg = (j0 >= 4 ? 1 : 0);
    const int b_ln  = b_nn * 4 + (j0 & 3);

    const float* xrow = X + (size_t)(m0 + lrow) * DIN;
    const float* wrow = W + (size_t)(n0 + lrow) * DIN;

    float acc[2][4][4];
#pragma unroll
    for (int mt = 0; mt < 2; mt++)
#pragma unroll
        for (int nt = 0; nt < 4; nt++)
#pragma unroll
            for (int r = 0; r < 4; r++) acc[mt][nt][r] = 0.f;

    // load slice 0 into buf 0
    {
        float4 xv = *(const float4*)&xrow[c0];
        uint h0, l0, h1, l1;
        split2(xv.x, xv.y, h0, l0);
        split2(xv.z, xv.w, h1, l1);
        As[0][0][a_mt][a_ln][a_reg] = h0;  As[0][0][a_mt][a_ln + 1][a_reg] = h1;
        As[0][1][a_mt][a_ln][a_reg] = l0;  As[0][1][a_mt][a_ln + 1][a_reg] = l1;
        float4 wv = *(const float4*)&wrow[c0];
        split2(wv.x, wv.y, h0, l0);
        split2(wv.z, wv.w, h1, l1);
        Bs[0][0][b_nt][b_ln][b_reg] = h0;  Bs[0][0][b_nt][b_ln + 1][b_reg] = h1;
        Bs[0][1][b_nt][b_ln][b_reg] = l0;  Bs[0][1][b_nt][b_ln + 1][b_reg] = l1;
    }
    __syncthreads();

    int buf = 0;
#pragma unroll 1
    for (int ks = 0; ks < 32; ks++) {
        if (ks + 1 < 32) {                 // prefetch next slice into buf^1
            int kk = (ks + 1) * 16 + c0;
            float4 xv = *(const float4*)&xrow[kk];
            uint h0, l0, h1, l1;
            split2(xv.x, xv.y, h0, l0);
            split2(xv.z, xv.w, h1, l1);
            As[buf ^ 1][0][a_mt][a_ln][a_reg] = h0;  As[buf ^ 1][0][a_mt][a_ln + 1][a_reg] = h1;
            As[buf ^ 1][1][a_mt][a_ln][a_reg] = l0;  As[buf ^ 1][1][a_mt][a_ln + 1][a_reg] = l1;
            float4 wv = *(const float4*)&wrow[kk];
            split2(wv.x, wv.y, h0, l0);
            split2(wv.z, wv.w, h1, l1);
            Bs[buf ^ 1][0][b_nt][b_ln][b_reg] = h0;  Bs[buf ^ 1][0][b_nt][b_ln + 1][b_reg] = h1;
            Bs[buf ^ 1][1][b_nt][b_ln][b_reg] = l0;  Bs[buf ^ 1][1][b_nt][b_ln + 1][b_reg] = l1;
        }
#pragma unroll
        for (int mt = 0; mt < 2; mt++) {
            uint4 Ah = *(uint4*)&As[buf][0][wm * 2 + mt][lane][0];
            uint4 Al = *(uint4*)&As[buf][1][wm * 2 + mt][lane][0];
#pragma unroll
            for (int nt = 0; nt < 4; nt++) {
                uint2 Bh = *(uint2*)&Bs[buf][0][wn * 4 + nt][lane][0];
                uint2 Bl = *(uint2*)&Bs[buf][1][wn * 4 + nt][lane][0];
                mma16816(acc[mt][nt], Ah.x, Ah.y, Ah.z, Ah.w, Bh.x, Bh.y);
                mma16816(acc[mt][nt], Al.x, Al.y, Al.z, Al.w, Bh.x, Bh.y);
                mma16816(acc[mt][nt], Ah.x, Ah.y, Ah.z, Ah.w, Bl.x, Bl.y);
            }
        }
        __syncthreads();
        buf ^= 1;
    }

    // epilogue: bias + store (rows m0+.., cols n0+..)
#pragma unroll
    for (int nt = 0; nt < 4; nt++) {
        int col = n0 + (wn * 4 + nt) * 8 + 2 * (lane & 3);
        float bx = bi[col] + bh[col];
        float by = bi[col + 1] + bh[col + 1];
#pragma unroll
        for (int mt = 0; mt < 2; mt++) {
            int row = m0 + (wm * 2 + mt) * 16 + (lane >> 2);
            float2 v0 = make_float2(acc[mt][nt][0] + bx, acc[mt][nt][1] + by);
            float2 v1 = make_float2(acc[mt][nt][2] + bx, acc[mt][nt][3] + by);
            *(float2*)&g_G0[(size_t)row * GATES + col] = v0;
            *(float2*)&g_G0[(size_t)(row + 8) * GATES + col] = v1;
        }
    }
}

// -------- k-loop: 3 independent accumulator chains, k-rotated (round-9) -------
__device__ __forceinline__ void run_phase3(
    const uint* __restrict__ ah_base, const uint* __restrict__ al_base,
    const uint4* __restrict__ bf_base, int mi, int lane, int rot,
    float dhh[4], float dlh[4], float dhl[4])
{
    const uint4* ah = (const uint4*)ah_base + (size_t)mi * 64 * 32 + lane;
    const uint4* al = (const uint4*)al_base + (size_t)mi * 64 * 32 + lane;
    const uint4* bf = bf_base + lane;
#pragma unroll 4
    for (int i = 0; i < 64; i++) {
        int ks = (i + rot) & 63;
        uint4 a_h = ah[ks * 32];
        uint4 a_l = al[ks * 32];
        uint4 bv  = __ldg(&bf[ks * 32]);
        mma16816(dhh, a_h.x, a_h.y, a_h.z, a_h.w, bv.x, bv.y);   // hi*hi
        mma16816(dlh, a_l.x, a_l.y, a_l.z, a_l.w, bv.x, bv.y);   // lo*hi
        mma16816(dhl, a_h.x, a_h.y, a_h.z, a_h.w, bv.z, bv.w);   // hi*lo
    }
}

// epilogue helper: split h to bf16 hi/lo and write A-fragment slots
__device__ __forceinline__ void store_hfrag(uint* dst_hi, uint* dst_lo,
                                            const float hf[8], int b, int cta) {
    int kstep = cta >> 1, khalf = cta & 1;
    int row = b & 15, mt = b >> 4;
    int regb = ((row >= 8) ? 1 : 0) + (khalf ? 2 : 0);
    int base = (mt * 64 + kstep) * 32 + (row & 7) * 4;
#pragma unroll
    for (int s = 0; s < 4; s++) {
        uint hi, lo;
        split2(hf[2 * s], hf[2 * s + 1], hi, lo);
        int idx = (base + s) * 4 + regb;
        dst_hi[idx] = hi;
        dst_lo[idx] = lo;
    }
}

// ---------------- persistent recurrent kernel (round-9, proven 25.3ms) --------
__global__ void __launch_bounds__(NTH) lstm_persistent(
    const float* __restrict__ bi1, const float* __restrict__ bh1,
    float* __restrict__ out)
{
    __shared__ float ds[64 * 33];          // D routing tile, pad 33 -> conflict-free

    const int tid  = threadIdx.x;
    const int lane = tid & 31;
    const int warp = tid >> 5;
    const int mi   = warp & 3;             // 16-row tile
    const int ni   = warp >> 2;            // 8-col tile
    const int cta  = blockIdx.x;
    const int u_start = cta * UPC;
    const int rot  = cta & 63;             // per-CTA k-rotation: de-camp L2 slices

    // zero parity-0 h fragments (first 65536 u32 of each array = parity 0 hi+lo)
    {
        int i0 = cta * NTH + tid;          // 0..65535
        ((uint*)g_h0f)[i0] = 0u;
        ((uint*)g_h1f)[i0] = 0u;
    }
    float c0r[8], c1r[8];
#pragma unroll
    for (int u = 0; u < 8; u++) { c0r[u] = 0.f; c1r[u] = 0.f; }
    float b1r[32];
    if (tid < 64) {
#pragma unroll
        for (int g = 0; g < 4; g++)
#pragma unroll
            for (int u = 0; u < 8; u++)
                b1r[g * 8 + u] = bi1[g * HID + u_start + u] + bh1[g * HID + u_start + u];
    }

    unsigned my_epoch = 0;
    grid_sync(my_epoch);

    const uint4* wf0 = g_wf + ((size_t)(cta * 3 + 0) * 4 + ni) * 2048;
    const uint4* wf1 = g_wf + ((size_t)(cta * 3 + 1) * 4 + ni) * 2048;
    const uint4* wf2 = g_wf + ((size_t)(cta * 3 + 2) * 4 + ni) * 2048;

    const int r0  = 16 * mi + (lane >> 2);
    const int cc0 = 8 * ni + (lane & 3) * 2;

    for (int t = 0; t < T_STEPS; t++) {
        const int par = t & 1, nxt = par ^ 1;

        // L2-prefetch this step's G0 slice (consumed ~20us later in epilogue 1)
        if (tid < 64) {
            const float* gp = g_G0 + ((size_t)t * BATCH + tid) * GATES + u_start;
            prefetchL2(gp);
            prefetchL2(gp + HID);
            prefetchL2(gp + 2 * HID);
            prefetchL2(gp + 3 * HID);
        }

        // ===== phase A: h1_prev@Whh1 (layer-1 partial, barrier-independent)
        //                + h0_prev@Whh0 (layer 0) =====
        float d1hh[4] = {0.f,0.f,0.f,0.f}, d1lh[4] = {0.f,0.f,0.f,0.f}, d1hl[4] = {0.f,0.f,0.f,0.f};
        run_phase3(g_h1f[par][0], g_h1f[par][1], wf2, mi, lane, rot, d1hh, d1lh, d1hl);
        {
            float dhh[4] = {0.f,0.f,0.f,0.f}, dlh[4] = {0.f,0.f,0.f,0.f}, dhl[4] = {0.f,0.f,0.f,0.f};
            run_phase3(g_h0f[par][0], g_h0f[par][1], wf0, mi, lane, rot, dhh, dlh, dhl);
            ds[r0 * 33 + cc0]           = dhh[0] + dlh[0] + dhl[0];
            ds[r0 * 33 + cc0 + 1]       = dhh[1] + dlh[1] + dhl[1];
            ds[(r0 + 8) * 33 + cc0]     = dhh[2] + dlh[2] + dhl[2];
            ds[(r0 + 8) * 33 + cc0 + 1] = dhh[3] + dlh[3] + dhl[3];
        }
        __syncthreads();
        if (tid < 64) {
            const int b = tid;
            const float* gp = g_G0 + ((size_t)t * BATCH + b) * GATES + u_start;
            float hf[8];
#pragma unroll
            for (int u = 0; u < 8; u++) {
                float gi = ds[b * 33 + u * 4 + 0] + gp[u];
                float gf = ds[b * 33 + u * 4 + 1] + gp[HID + u];
                float gg = ds[b * 33 + u * 4 + 2] + gp[2 * HID + u];
                float go = ds[b * 33 + u * 4 + 3] + gp[3 * HID + u];
                float c = sigmoidf_(gf) * c0r[u] + sigmoidf_(gi) * tanhf(gg);
                c0r[u] = c;
                hf[u] = sigmoidf_(go) * tanhf(c);
            }
            store_hfrag(g_h0f[nxt][0], g_h0f[nxt][1], hf, b, cta);
            if (t == T_STEPS - 1) {
                float* so = out + (size_t)T_STEPS * BATCH * HID;
#pragma unroll
                for (int u = 0; u < 8; u++) {
                    so[b * HID + u_start + u]         = hf[u];
                    so[65536 + b * HID + u_start + u] = c0r[u];
                }
            }
        }
        grid_sync(my_epoch);

        // ===== phase B: += h0_new@Wih1 (layer-1 remainder) =====
        run_phase3(g_h0f[nxt][0], g_h0f[nxt][1], wf1, mi, lane, rot, d1hh, d1lh, d1hl);
        ds[r0 * 33 + cc0]           = d1hh[0] + d1lh[0] + d1hl[0];
        ds[r0 * 33 + cc0 + 1]       = d1hh[1] + d1lh[1] + d1hl[1];
        ds[(r0 + 8) * 33 + cc0]     = d1hh[2] + d1lh[2] + d1hl[2];
        ds[(r0 + 8) * 33 + cc0 + 1] = d1hh[3] + d1lh[3] + d1hl[3];
        __syncthreads();
        if (tid < 64) {
            const int b = tid;
            float hf[8];
#pragma unroll
            for (int u = 0; u < 8; u++) {
                float gi = ds[b * 33 + u * 4 + 0] + b1r[u];
                float gf = ds[b * 33 + u * 4 + 1] + b1r[8 + u];
                float gg = ds[b * 33 + u * 4 + 2] + b1r[16 + u];
                float go = ds[b * 33 + u * 4 + 3] + b1r[24 + u];
                float c = sigmoidf_(gf) * c1r[u] + sigmoidf_(gi) * tanhf(gg);
                c1r[u] = c;
                hf[u] = sigmoidf_(go) * tanhf(c);
            }
            store_hfrag(g_h1f[nxt][0], g_h1f[nxt][1], hf, b, cta);
            float* orow = out + ((size_t)t * BATCH + b) * HID + u_start;
            *(float4*)&orow[0] = make_float4(hf[0], hf[1], hf[2], hf[3]);
            *(float4*)&orow[4] = make_float4(hf[4], hf[5], hf[6], hf[7]);
            if (t == T_STEPS - 1) {
                float* so = out + (size_t)T_STEPS * BATCH * HID;
#pragma unroll
                for (int u = 0; u < 8; u++) {
                    so[131072 + b * HID + u_start + u] = hf[u];
                    so[196608 + b * HID + u_start + u] = c1r[u];
                }
            }
        }
        grid_sync(my_epoch);
    }

    // ---- reset barrier vars for deterministic graph replay ----
    __threadfence();
    __syncthreads();
    if (tid == 0) {
        if (atomicAdd(&g_done_cnt, 1u) == (unsigned)NB - 1u) {
            g_done_cnt = 0u;
            g_bar_cnt  = 0u;
            __threadfence();
            g_bar_epoch = 0u;
        }
    }
}

// ---------------- launch ------------------------------------------------------
extern "C" void kernel_launch(void* const* d_in, const int* in_sizes, int n_in,
                              void* d_out, int out_size) {
    const float* X     = (const float*)d_in[0];
    const float* Wih0  = (const float*)d_in[1];
    const float* Whh0  = (const float*)d_in[2];
    const float* bih0  = (const float*)d_in[3];
    const float* bhh0  = (const float*)d_in[4];
    const float* Wih1  = (const float*)d_in[5];
    const float* Whh1  = (const float*)d_in[6];
    const float* bih1  = (const float*)d_in[7];
    const float* bhh1  = (const float*)d_in[8];
    float* out = (float*)d_out;

    prep_w<<<12288, 256>>>(Whh0, Wih1, Whh1);

    dim3 ggrid(GATES / 128, (T_STEPS * BATCH) / 128);   // 32 x 256 blocks
    gemm_g0_bf16<<<ggrid, 512>>>(X, Wih0, bih0, bhh0);

    lstm_persistent<<<NB, NTH>>>(bih1, bhh1, out);
}

// round 14
// speedup vs baseline: 1.6729x; 1.1359x over previous
#include <cuda_runtime.h>
#include <cuda_bf16.h>
#include <cuda_fp16.h>
#include <cstdint>

typedef unsigned long long ull;
typedef unsigned int uint;

#define T_STEPS 512
#define BATCH   64
#define DIN     512
#define HID     1024
#define GATES   4096
#define NB      128          // persistent grid: 128 CTAs x 8 units = 1024
#define NTH     512          // 16 warps: mi = w&3 (16-row), ni = w>>2 (8-col)
#define UPC     8

// ---------------- scratch -----------------------------------------------------
__device__ float g_G0[(size_t)T_STEPS * BATCH * GATES];       // X@Wih0^T + biases
// weights in per-lane B-fragment order (fp16): [cta][mat 3][ni 4][kstep 64][lane 32]
// uint4 = {b0_hi, b1_hi, b0_lo, b1_lo}
__device__ uint4 g_wf[(size_t)NB * 3 * 4 * 64 * 32];
// hidden states, SINGLE fp16 plane, A-fragment order:
// [parity][((mt*64+ks)*32+lane)*4+reg]
__device__ uint g_h0f[2][32768];
__device__ uint g_h1f[2][32768];
__device__ unsigned g_bar_cnt;
__device__ volatile unsigned g_bar_epoch;
__device__ unsigned g_done_cnt;

// ---------------- helpers -----------------------------------------------------
__device__ __forceinline__ float sigmoidf_(float x) { return 1.0f / (1.0f + expf(-x)); }

// fp16 mma m16n8k16
__device__ __forceinline__ void mmah(float d[4], uint4 A, uint b0, uint b1) {
    asm volatile("mma.sync.aligned.m16n8k16.row.col.f32.f16.f16.f32 "
        "{%0,%1,%2,%3}, {%4,%5,%6,%7}, {%8,%9}, {%0,%1,%2,%3};"
        : "+f"(d[0]), "+f"(d[1]), "+f"(d[2]), "+f"(d[3])
        : "r"(A.x), "r"(A.y), "r"(A.z), "r"(A.w), "r"(b0), "r"(b1));
}
// bf16 mma (gemm_g0 only)
__device__ __forceinline__ void mma16816(float d[4], uint a0, uint a1, uint a2, uint a3,
                                         uint b0, uint b1) {
    asm volatile("mma.sync.aligned.m16n8k16.row.col.f32.bf16.bf16.f32 "
        "{%0,%1,%2,%3}, {%4,%5,%6,%7}, {%8,%9}, {%0,%1,%2,%3};"
        : "+f"(d[0]), "+f"(d[1]), "+f"(d[2]), "+f"(d[3])
        : "r"(a0), "r"(a1), "r"(a2), "r"(a3), "r"(b0), "r"(b1));
}

__device__ __forceinline__ void prefetchL2(const void* p) {
    asm volatile("prefetch.global.L2 [%0];" :: "l"(p));
}

__device__ __forceinline__ void grid_sync(unsigned &my_epoch) {
    __threadfence();
    __syncthreads();
    if (threadIdx.x == 0) {
        my_epoch++;
        if (atomicAdd(&g_bar_cnt, 1u) == (unsigned)NB - 1u) {
            g_bar_cnt = 0u;
            __threadfence();
            g_bar_epoch = my_epoch;
        } else {
            while (g_bar_epoch < my_epoch) { }
            __threadfence();
        }
    }
    __syncthreads();
}

// bf16 pack/split (gemm_g0)
__device__ __forceinline__ uint pack_bf2(__nv_bfloat16 lo16, __nv_bfloat16 hi16) {
    return (uint)__bfloat16_as_ushort(lo16) | ((uint)__bfloat16_as_ushort(hi16) << 16);
}
__device__ __forceinline__ void split2(float x, float y, uint &hi, uint &lo) {
    __nv_bfloat16 xh = __float2bfloat16(x), yh = __float2bfloat16(y);
    hi = pack_bf2(xh, yh);
    lo = pack_bf2(__float2bfloat16(x - __bfloat162float(xh)),
                  __float2bfloat16(y - __bfloat162float(yh)));
}
// fp16 pack/split (recurrent path)
__device__ __forceinline__ uint pack_h2(__half a, __half b) {
    return (uint)__half_as_ushort(a) | ((uint)__half_as_ushort(b) << 16);
}
__device__ __forceinline__ void split2h(float x, float y, uint &hi, uint &lo) {
    __half xh = __float2half_rn(x), yh = __float2half_rn(y);
    hi = pack_h2(xh, yh);
    lo = pack_h2(__float2half_rn(x - __half2float(xh)),
                 __float2half_rn(y - __half2float(yh)));
}

// ---------------- prep: weights -> B-fragment order, fp16 hi/lo ---------------
__global__ void __launch_bounds__(256) prep_w(
    const float* __restrict__ Whh0, const float* __restrict__ Wih1,
    const float* __restrict__ Whh1)
{
    uint idx = blockIdx.x * 256u + threadIdx.x;
    uint lane = idx & 31u;
    uint ks   = (idx >> 5) & 63u;
    uint ni   = (idx >> 11) & 3u;
    uint cm   = idx >> 13;
    uint mat  = cm % 3u, cta = cm / 3u;

    const float* W = (mat == 0) ? Whh0 : (mat == 1) ? Wih1 : Whh1;
    uint n  = ni * 8u + (lane >> 2);       // col within CTA's 32: n = lu*4 + g
    uint lu = n >> 2, g = n & 3u;
    const float* row = W + (size_t)(g * HID + cta * UPC + lu) * HID;
    uint k0 = ks * 16u + (lane & 3u) * 2u;

    float f0 = row[k0],     f1 = row[k0 + 1];
    float f2 = row[k0 + 8], f3 = row[k0 + 9];
    uint4 v;
    split2h(f0, f1, v.x, v.z);
    split2h(f2, f3, v.y, v.w);
    g_wf[idx] = v;
}

// ---------------- tensorized G0 GEMM (round-12, proven) -----------------------
__global__ void __launch_bounds__(512) gemm_g0_bf16(
    const float* __restrict__ X, const float* __restrict__ W,
    const float* __restrict__ bi, const float* __restrict__ bh)
{
    __shared__ uint As[2][2][8][32][4];
    __shared__ uint Bs[2][2][16][32][2];

    const int tid  = threadIdx.x;
    const int lane = tid & 31;
    const int warp = tid >> 5;
    const int wm   = warp >> 2;
    const int wn   = warp & 3;
    const int m0 = blockIdx.y * 128, n0 = blockIdx.x * 128;

    const int lrow = tid >> 2;
    const int c0   = (tid & 3) * 4;
    const int j0   = c0 >> 1;
    const int a_mt  = lrow >> 4, a_rr = lrow & 15;
    const int a_reg = (a_rr >= 8 ? 1 : 0) + (j0 >= 4 ? 2 : 0);
    const int a_ln  = (a_rr & 7) * 4 + (j0 & 3);
    const int b_nt  = lrow >> 3, b_nn = lrow & 7;
    const int b_reg = (j0 >= 4 ? 1 : 0);
    const int b_ln  = b_nn * 4 + (j0 & 3);

    const float* xrow = X + (size_t)(m0 + lrow) * DIN;
    const float* wrow = W + (size_t)(n0 + lrow) * DIN;

    float acc[2][4][4];
#pragma unroll
    for (int mt = 0; mt < 2; mt++)
#pragma unroll
        for (int nt = 0; nt < 4; nt++)
#pragma unroll
            for (int r = 0; r < 4; r++) acc[mt][nt][r] = 0.f;

    {
        float4 xv = *(const float4*)&xrow[c0];
        uint h0, l0, h1, l1;
        split2(xv.x, xv.y, h0, l0);
        split2(xv.z, xv.w, h1, l1);
        As[0][0][a_mt][a_ln][a_reg] = h0;  As[0][0][a_mt][a_ln + 1][a_reg] = h1;
        As[0][1][a_mt][a_ln][a_reg] = l0;  As[0][1][a_mt][a_ln + 1][a_reg] = l1;
        float4 wv = *(const float4*)&wrow[c0];
        split2(wv.x, wv.y, h0, l0);
        split2(wv.z, wv.w, h1, l1);
        Bs[0][0][b_nt][b_ln][b_reg] = h0;  Bs[0][0][b_nt][b_ln + 1][b_reg] = h1;
        Bs[0][1][b_nt][b_ln][b_reg] = l0;  Bs[0][1][b_nt][b_ln + 1][b_reg] = l1;
    }
    __syncthreads();

    int buf = 0;
#pragma unroll 1
    for (int ks = 0; ks < 32; ks++) {
        if (ks + 1 < 32) {
            int kk = (ks + 1) * 16 + c0;
            float4 xv = *(const float4*)&xrow[kk];
            uint h0, l0, h1, l1;
            split2(xv.x, xv.y, h0, l0);
            split2(xv.z, xv.w, h1, l1);
            As[buf ^ 1][0][a_mt][a_ln][a_reg] = h0;  As[buf ^ 1][0][a_mt][a_ln + 1][a_reg] = h1;
            As[buf ^ 1][1][a_mt][a_ln][a_reg] = l0;  As[buf ^ 1][1][a_mt][a_ln + 1][a_reg] = l1;
            float4 wv = *(const float4*)&wrow[kk];
            split2(wv.x, wv.y, h0, l0);
            split2(wv.z, wv.w, h1, l1);
            Bs[buf ^ 1][0][b_nt][b_ln][b_reg] = h0;  Bs[buf ^ 1][0][b_nt][b_ln + 1][b_reg] = h1;
            Bs[buf ^ 1][1][b_nt][b_ln][b_reg] = l0;  Bs[buf ^ 1][1][b_nt][b_ln + 1][b_reg] = l1;
        }
#pragma unroll
        for (int mt = 0; mt < 2; mt++) {
            uint4 Ah = *(uint4*)&As[buf][0][wm * 2 + mt][lane][0];
            uint4 Al = *(uint4*)&As[buf][1][wm * 2 + mt][lane][0];
#pragma unroll
            for (int nt = 0; nt < 4; nt++) {
                uint2 Bh = *(uint2*)&Bs[buf][0][wn * 4 + nt][lane][0];
                uint2 Bl = *(uint2*)&Bs[buf][1][wn * 4 + nt][lane][0];
                mma16816(acc[mt][nt], Ah.x, Ah.y, Ah.z, Ah.w, Bh.x, Bh.y);
                mma16816(acc[mt][nt], Al.x, Al.y, Al.z, Al.w, Bh.x, Bh.y);
                mma16816(acc[mt][nt], Ah.x, Ah.y, Ah.z, Ah.w, Bl.x, Bl.y);
            }
        }
        __syncthreads();
        buf ^= 1;
    }

#pragma unroll
    for (int nt = 0; nt < 4; nt++) {
        int col = n0 + (wn * 4 + nt) * 8 + 2 * (lane & 3);
        float bx = bi[col] + bh[col];
        float by = bi[col + 1] + bh[col + 1];
#pragma unroll
        for (int mt = 0; mt < 2; mt++) {
            int row = m0 + (wm * 2 + mt) * 16 + (lane >> 2);
            float2 v0 = make_float2(acc[mt][nt][0] + bx, acc[mt][nt][1] + by);
            float2 v1 = make_float2(acc[mt][nt][2] + bx, acc[mt][nt][3] + by);
            *(float2*)&g_G0[(size_t)row * GATES + col] = v0;
            *(float2*)&g_G0[(size_t)(row + 8) * GATES + col] = v1;
        }
    }
}

// -------- phase A: fused h1@Whh1 + h0@Whh0, 4 indep chains, 64 iters ----------
__device__ __forceinline__ void run_phaseA(
    const uint* __restrict__ a1_base, const uint* __restrict__ a0_base,
    const uint4* __restrict__ wf2, const uint4* __restrict__ wf0,
    int mi, int lane, int rot,
    float d1h[4], float d1l[4], float d0h[4], float d0l[4])
{
    const uint4* a1 = (const uint4*)a1_base + (size_t)mi * 2048 + lane;
    const uint4* a0 = (const uint4*)a0_base + (size_t)mi * 2048 + lane;
    const uint4* b2 = wf2 + lane;
    const uint4* b0 = wf0 + lane;
#pragma unroll 4
    for (int i = 0; i < 64; i++) {
        int off = ((i + rot) & 63) * 32;
        uint4 A1 = a1[off];
        uint4 B2 = __ldg(&b2[off]);
        uint4 A0 = a0[off];
        uint4 B0 = __ldg(&b0[off]);
        mmah(d1h, A1, B2.x, B2.y);
        mmah(d1l, A1, B2.z, B2.w);
        mmah(d0h, A0, B0.x, B0.y);
        mmah(d0l, A0, B0.z, B0.w);
    }
}

// -------- phase B: h0_new@Wih1, 2 chains --------------------------------------
__device__ __forceinline__ void run_phaseB(
    const uint* __restrict__ a_base, const uint4* __restrict__ wf1,
    int mi, int lane, int rot, float dh[4], float dl[4])
{
    const uint4* a = (const uint4*)a_base + (size_t)mi * 2048 + lane;
    const uint4* bf = wf1 + lane;
#pragma unroll 4
    for (int i = 0; i < 64; i++) {
        int off = ((i + rot) & 63) * 32;
        uint4 A = a[off];
        uint4 B = __ldg(&bf[off]);
        mmah(dh, A, B.x, B.y);
        mmah(dl, A, B.z, B.w);
    }
}

// ---------------- persistent recurrent kernel ---------------------------------
__global__ void __launch_bounds__(NTH) lstm_persistent(
    const float* __restrict__ bi1, const float* __restrict__ bh1,
    float* __restrict__ out)
{
    __shared__ float ds[64 * 33];          // D routing tile, pad 33 -> conflict-free

    const int tid  = threadIdx.x;
    const int lane = tid & 31;
    const int warp = tid >> 5;
    const int mi   = warp & 3;             // 16-row tile
    const int ni   = warp >> 2;            // 8-col tile
    const int cta  = blockIdx.x;
    const int u_start = cta * UPC;
    const int rot  = cta & 63;             // per-CTA k-rotation: de-camp L2 slices

    // epilogue thread mapping: tid<256 -> (b, s): units 2s, 2s+1 of this CTA
    const int eb = tid & 63;
    const int es = tid >> 6;               // 0..3 when tid<256

    // zero parity-0 h fragments
    {
        int i0 = cta * NTH + tid;          // 0..65535
        if (i0 < 32768) { g_h0f[0][i0] = 0u; g_h1f[0][i0] = 0u; }
    }
    float c0r[2] = {0.f, 0.f}, c1r[2] = {0.f, 0.f};
    float b1r[8];
    if (tid < 256) {
#pragma unroll
        for (int g = 0; g < 4; g++)
#pragma unroll
            for (int j = 0; j < 2; j++)
                b1r[g * 2 + j] = bi1[g * HID + u_start + 2 * es + j]
                               + bh1[g * HID + u_start + 2 * es + j];
    }
    // fragment store slot for this epilogue thread
    const int f_kstep = cta >> 1, f_khalf = cta & 1;
    const int f_row = eb & 15, f_mt = eb >> 4;
    const int f_reg = ((f_row >= 8) ? 1 : 0) + (f_khalf ? 2 : 0);
    const int f_idx = (((f_mt * 64 + f_kstep) * 32 + (f_row & 7) * 4) + es) * 4 + f_reg;

    unsigned my_epoch = 0;
    grid_sync(my_epoch);

    const uint4* wf0 = g_wf + ((size_t)(cta * 3 + 0) * 4 + ni) * 2048;  // Whh0
    const uint4* wf1 = g_wf + ((size_t)(cta * 3 + 1) * 4 + ni) * 2048;  // Wih1
    const uint4* wf2 = g_wf + ((size_t)(cta * 3 + 2) * 4 + ni) * 2048;  // Whh1

    const int r0  = 16 * mi + (lane >> 2);
    const int cc0 = 8 * ni + (lane & 3) * 2;

    for (int t = 0; t < T_STEPS; t++) {
        const int par = t & 1, nxt = par ^ 1;

        // L2-prefetch this step's G0 slice
        if (tid < 64) {
            const float* gp = g_G0 + ((size_t)t * BATCH + tid) * GATES + u_start;
            prefetchL2(gp);
            prefetchL2(gp + HID);
            prefetchL2(gp + 2 * HID);
            prefetchL2(gp + 3 * HID);
        }

        // ===== phase A: h1_prev@Whh1 (carry) + h0_prev@Whh0 (layer 0) =====
        float d1h[4] = {0.f,0.f,0.f,0.f}, d1l[4] = {0.f,0.f,0.f,0.f};
        {
            float d0h[4] = {0.f,0.f,0.f,0.f}, d0l[4] = {0.f,0.f,0.f,0.f};
            run_phaseA(g_h1f[par], g_h0f[par], wf2, wf0, mi, lane, rot,
                       d1h, d1l, d0h, d0l);
            ds[r0 * 33 + cc0]           = d0h[0] + d0l[0];
            ds[r0 * 33 + cc0 + 1]       = d0h[1] + d0l[1];
            ds[(r0 + 8) * 33 + cc0]     = d0h[2] + d0l[2];
            ds[(r0 + 8) * 33 + cc0 + 1] = d0h[3] + d0l[3];
        }
        __syncthreads();
        if (tid < 256) {                    // layer-0 epilogue: thread = (b, unit pair)
            const float* gp = g_G0 + ((size_t)t * BATCH + eb) * GATES + u_start + 2 * es;
            float hf[2];
#pragma unroll
            for (int j = 0; j < 2; j++) {
                int u = 2 * es + j;
                float gi = ds[eb * 33 + u * 4 + 0] + gp[j];
                float gf = ds[eb * 33 + u * 4 + 1] + gp[HID + j];
                float gg = ds[eb * 33 + u * 4 + 2] + gp[2 * HID + j];
                float go = ds[eb * 33 + u * 4 + 3] + gp[3 * HID + j];
                float c = sigmoidf_(gf) * c0r[j] + sigmoidf_(gi) * tanhf(gg);
                c0r[j] = c;
                hf[j] = sigmoidf_(go) * tanhf(c);
            }
            g_h0f[nxt][f_idx] = pack_h2(__float2half_rn(hf[0]), __float2half_rn(hf[1]));
            if (t == T_STEPS - 1) {
                float* so = out + (size_t)T_STEPS * BATCH * HID;
                int u0 = u_start + 2 * es;
                *(float2*)&so[eb * HID + u0]         = make_float2(hf[0], hf[1]);
                *(float2*)&so[65536 + eb * HID + u0] = make_float2(c0r[0], c0r[1]);
            }
        }
        grid_sync(my_epoch);

        // ===== phase B: += h0_new@Wih1 (layer-1 remainder) =====
        run_phaseB(g_h0f[nxt], wf1, mi, lane, rot, d1h, d1l);
        ds[r0 * 33 + cc0]           = d1h[0] + d1l[0];
        ds[r0 * 33 + cc0 + 1]       = d1h[1] + d1l[1];
        ds[(r0 + 8) * 33 + cc0]     = d1h[2] + d1l[2];
        ds[(r0 + 8) * 33 + cc0 + 1] = d1h[3] + d1l[3];
        __syncthreads();
        if (tid < 256) {                    // layer-1 epilogue
            float hf[2];
#pragma unroll
            for (int j = 0; j < 2; j++) {
                int u = 2 * es + j;
                float gi = ds[eb * 33 + u * 4 + 0] + b1r[j];
                float gf = ds[eb * 33 + u * 4 + 1] + b1r[2 + j];
                float gg = ds[eb * 33 + u * 4 + 2] + b1r[4 + j];
                float go = ds[eb * 33 + u * 4 + 3] + b1r[6 + j];
                float c = sigmoidf_(gf) * c1r[j] + sigmoidf_(gi) * tanhf(gg);
                c1r[j] = c;
                hf[j] = sigmoidf_(go) * tanhf(c);
            }
            g_h1f[nxt][f_idx] = pack_h2(__float2half_rn(hf[0]), __float2half_rn(hf[1]));
            int u0 = u_start + 2 * es;
            *(float2*)&out[((size_t)t * BATCH + eb) * HID + u0] = make_float2(hf[0], hf[1]);
            if (t == T_STEPS - 1) {
                float* so = out + (size_t)T_STEPS * BATCH * HID;
                *(float2*)&so[131072 + eb * HID + u0] = make_float2(hf[0], hf[1]);
                *(float2*)&so[196608 + eb * HID + u0] = make_float2(c1r[0], c1r[1]);
            }
        }
        grid_sync(my_epoch);
    }

    // ---- reset barrier vars for deterministic graph replay ----
    __threadfence();
    __syncthreads();
    if (tid == 0) {
        if (atomicAdd(&g_done_cnt, 1u) == (unsigned)NB - 1u) {
            g_done_cnt = 0u;
            g_bar_cnt  = 0u;
            __threadfence();
            g_bar_epoch = 0u;
        }
    }
}

// ---------------- launch ------------------------------------------------------
extern "C" void kernel_launch(void* const* d_in, const int* in_sizes, int n_in,
                              void* d_out, int out_size) {
    const float* X     = (const float*)d_in[0];
    const float* Wih0  = (const float*)d_in[1];
    const float* Whh0  = (const float*)d_in[2];
    const float* bih0  = (const float*)d_in[3];
    const float* bhh0  = (const float*)d_in[4];
    const float* Wih1  = (const float*)d_in[5];
    const float* Whh1  = (const float*)d_in[6];
    const float* bih1  = (const float*)d_in[7];
    const float* bhh1  = (const float*)d_in[8];
    float* out = (float*)d_out;

    prep_w<<<12288, 256>>>(Whh0, Wih1, Whh1);

    dim3 ggrid(GATES / 128, (T_STEPS * BATCH) / 128);   // 32 x 256 blocks
    gemm_g0_bf16<<<ggrid, 512>>>(X, Wih0, bih0, bhh0);

    lstm_persistent<<<NB, NTH>>>(bih1, bhh1, out);
}

// round 15
// speedup vs baseline: 1.9449x; 1.1626x over previous
#include <cuda_runtime.h>
#include <cuda_bf16.h>
#include <cuda_fp16.h>
#include <cstdint>

typedef unsigned long long ull;
typedef unsigned int uint;

#define T_STEPS 512
#define BATCH   64
#define DIN     512
#define HID     1024
#define GATES   4096
#define NB      128          // persistent grid: 128 CTAs x 8 units = 1024
#define NTH     512          // 16 warps: mi = w&3 (16-row), ni = w>>2 (8-col)
#define UPC     8

// dynamic SMEM: weight slab, 3 mats x 4 ni x 64 ks x 32 lanes x uint2 = 196608 B
#define WSM_U2  (3 * 4 * 64 * 32)

// ---------------- scratch -----------------------------------------------------
__device__ float g_G0[(size_t)T_STEPS * BATCH * GATES];       // X@Wih0^T + biases
// weights, SINGLE fp16 plane, per-lane B-fragment order:
// [cta][mat 3][ni 4][kstep 64][lane 32] ; uint2 = {b0, b1}
__device__ uint2 g_wf[(size_t)NB * WSM_U2];
// hidden states, SINGLE fp16 plane, A-fragment order:
// [parity][((mt*64+ks)*32+lane)*4+reg]
__device__ uint g_h0f[2][32768];
__device__ uint g_h1f[2][32768];
__device__ unsigned g_bar_cnt;
__device__ volatile unsigned g_bar_epoch;
__device__ unsigned g_done_cnt;

// ---------------- helpers -----------------------------------------------------
__device__ __forceinline__ float sigmoidf_(float x) { return 1.0f / (1.0f + expf(-x)); }

// fp16 mma m16n8k16
__device__ __forceinline__ void mmah(float d[4], uint4 A, uint b0, uint b1) {
    asm volatile("mma.sync.aligned.m16n8k16.row.col.f32.f16.f16.f32 "
        "{%0,%1,%2,%3}, {%4,%5,%6,%7}, {%8,%9}, {%0,%1,%2,%3};"
        : "+f"(d[0]), "+f"(d[1]), "+f"(d[2]), "+f"(d[3])
        : "r"(A.x), "r"(A.y), "r"(A.z), "r"(A.w), "r"(b0), "r"(b1));
}
// bf16 mma (gemm_g0 only)
__device__ __forceinline__ void mma16816(float d[4], uint a0, uint a1, uint a2, uint a3,
                                         uint b0, uint b1) {
    asm volatile("mma.sync.aligned.m16n8k16.row.col.f32.bf16.bf16.f32 "
        "{%0,%1,%2,%3}, {%4,%5,%6,%7}, {%8,%9}, {%0,%1,%2,%3};"
        : "+f"(d[0]), "+f"(d[1]), "+f"(d[2]), "+f"(d[3])
        : "r"(a0), "r"(a1), "r"(a2), "r"(a3), "r"(b0), "r"(b1));
}

__device__ __forceinline__ void prefetchL2(const void* p) {
    asm volatile("prefetch.global.L2 [%0];" :: "l"(p));
}

__device__ __forceinline__ void grid_sync(unsigned &my_epoch) {
    __threadfence();
    __syncthreads();
    if (threadIdx.x == 0) {
        my_epoch++;
        if (atomicAdd(&g_bar_cnt, 1u) == (unsigned)NB - 1u) {
            g_bar_cnt = 0u;
            __threadfence();
            g_bar_epoch = my_epoch;
        } else {
            while (g_bar_epoch < my_epoch) { }
            __threadfence();
        }
    }
    __syncthreads();
}

// bf16 pack/split (gemm_g0)
__device__ __forceinline__ uint pack_bf2(__nv_bfloat16 lo16, __nv_bfloat16 hi16) {
    return (uint)__bfloat16_as_ushort(lo16) | ((uint)__bfloat16_as_ushort(hi16) << 16);
}
__device__ __forceinline__ void split2(float x, float y, uint &hi, uint &lo) {
    __nv_bfloat16 xh = __float2bfloat16(x), yh = __float2bfloat16(y);
    hi = pack_bf2(xh, yh);
    lo = pack_bf2(__float2bfloat16(x - __bfloat162float(xh)),
                  __float2bfloat16(y - __bfloat162float(yh)));
}
// fp16 pack
__device__ __forceinline__ uint pack_h2(__half a, __half b) {
    return (uint)__half_as_ushort(a) | ((uint)__half_as_ushort(b) << 16);
}

// ---------------- prep: weights -> B-fragment order, single fp16 --------------
__global__ void __launch_bounds__(256) prep_w(
    const float* __restrict__ Whh0, const float* __restrict__ Wih1,
    const float* __restrict__ Whh1)
{
    uint idx = blockIdx.x * 256u + threadIdx.x;
    uint lane = idx & 31u;
    uint ks   = (idx >> 5) & 63u;
    uint ni   = (idx >> 11) & 3u;
    uint cm   = idx >> 13;
    uint mat  = cm % 3u, cta = cm / 3u;

    const float* W = (mat == 0) ? Whh0 : (mat == 1) ? Wih1 : Whh1;
    uint n  = ni * 8u + (lane >> 2);       // col within CTA's 32: n = lu*4 + g
    uint lu = n >> 2, g = n & 3u;
    const float* row = W + (size_t)(g * HID + cta * UPC + lu) * HID;
    uint k0 = ks * 16u + (lane & 3u) * 2u;

    uint2 v;
    v.x = pack_h2(__float2half_rn(row[k0]),     __float2half_rn(row[k0 + 1]));
    v.y = pack_h2(__float2half_rn(row[k0 + 8]), __float2half_rn(row[k0 + 9]));
    // destination index: [cta][mat][ni][ks][lane]
    g_wf[(((size_t)(cta * 3 + mat) * 4 + ni) * 64 + ks) * 32 + lane] = v;
}

// ---------------- tensorized G0 GEMM (round-12, proven) -----------------------
__global__ void __launch_bounds__(512) gemm_g0_bf16(
    const float* __restrict__ X, const float* __restrict__ W,
    const float* __restrict__ bi, const float* __restrict__ bh)
{
    __shared__ uint As[2][2][8][32][4];
    __shared__ uint Bs[2][2][16][32][2];

    const int tid  = threadIdx.x;
    const int lane = tid & 31;
    const int warp = tid >> 5;
    const int wm   = warp >> 2;
    const int wn   = warp & 3;
    const int m0 = blockIdx.y * 128, n0 = blockIdx.x * 128;

    const int lrow = tid >> 2;
    const int c0   = (tid & 3) * 4;
    const int j0   = c0 >> 1;
    const int a_mt  = lrow >> 4, a_rr = lrow & 15;
    const int a_reg = (a_rr >= 8 ? 1 : 0) + (j0 >= 4 ? 2 : 0);
    const int a_ln  = (a_rr & 7) * 4 + (j0 & 3);
    const int b_nt  = lrow >> 3, b_nn = lrow & 7;
    const int b_reg = (j0 >= 4 ? 1 : 0);
    const int b_ln  = b_nn * 4 + (j0 & 3);

    const float* xrow = X + (size_t)(m0 + lrow) * DIN;
    const float* wrow = W + (size_t)(n0 + lrow) * DIN;

    float acc[2][4][4];
#pragma unroll
    for (int mt = 0; mt < 2; mt++)
#pragma unroll
        for (int nt = 0; nt < 4; nt++)
#pragma unroll
            for (int r = 0; r < 4; r++) acc[mt][nt][r] = 0.f;

    {
        float4 xv = *(const float4*)&xrow[c0];
        uint h0, l0, h1, l1;
        split2(xv.x, xv.y, h0, l0);
        split2(xv.z, xv.w, h1, l1);
        As[0][0][a_mt][a_ln][a_reg] = h0;  As[0][0][a_mt][a_ln + 1][a_reg] = h1;
        As[0][1][a_mt][a_ln][a_reg] = l0;  As[0][1][a_mt][a_ln + 1][a_reg] = l1;
        float4 wv = *(const float4*)&wrow[c0];
        split2(wv.x, wv.y, h0, l0);
        split2(wv.z, wv.w, h1, l1);
        Bs[0][0][b_nt][b_ln][b_reg] = h0;  Bs[0][0][b_nt][b_ln + 1][b_reg] = h1;
        Bs[0][1][b_nt][b_ln][b_reg] = l0;  Bs[0][1][b_nt][b_ln + 1][b_reg] = l1;
    }
    __syncthreads();

    int buf = 0;
#pragma unroll 1
    for (int ks = 0; ks < 32; ks++) {
        if (ks + 1 < 32) {
            int kk = (ks + 1) * 16 + c0;
            float4 xv = *(const float4*)&xrow[kk];
            uint h0, l0, h1, l1;
            split2(xv.x, xv.y, h0, l0);
            split2(xv.z, xv.w, h1, l1);
            As[buf ^ 1][0][a_mt][a_ln][a_reg] = h0;  As[buf ^ 1][0][a_mt][a_ln + 1][a_reg] = h1;
            As[buf ^ 1][1][a_mt][a_ln][a_reg] = l0;  As[buf ^ 1][1][a_mt][a_ln + 1][a_reg] = l1;
            float4 wv = *(const float4*)&wrow[kk];
            split2(wv.x, wv.y, h0, l0);
            split2(wv.z, wv.w, h1, l1);
            Bs[buf ^ 1][0][b_nt][b_ln][b_reg] = h0;  Bs[buf ^ 1][0][b_nt][b_ln + 1][b_reg] = h1;
            Bs[buf ^ 1][1][b_nt][b_ln][b_reg] = l0;  Bs[buf ^ 1][1][b_nt][b_ln + 1][b_reg] = l1;
        }
#pragma unroll
        for (int mt = 0; mt < 2; mt++) {
            uint4 Ah = *(uint4*)&As[buf][0][wm * 2 + mt][lane][0];
            uint4 Al = *(uint4*)&As[buf][1][wm * 2 + mt][lane][0];
#pragma unroll
            for (int nt = 0; nt < 4; nt++) {
                uint2 Bh = *(uint2*)&Bs[buf][0][wn * 4 + nt][lane][0];
                uint2 Bl = *(uint2*)&Bs[buf][1][wn * 4 + nt][lane][0];
                mma16816(acc[mt][nt], Ah.x, Ah.y, Ah.z, Ah.w, Bh.x, Bh.y);
                mma16816(acc[mt][nt], Al.x, Al.y, Al.z, Al.w, Bh.x, Bh.y);
                mma16816(acc[mt][nt], Ah.x, Ah.y, Ah.z, Ah.w, Bl.x, Bl.y);
            }
        }
        __syncthreads();
        buf ^= 1;
    }

#pragma unroll
    for (int nt = 0; nt < 4; nt++) {
        int col = n0 + (wn * 4 + nt) * 8 + 2 * (lane & 3);
        float bx = bi[col] + bh[col];
        float by = bi[col + 1] + bh[col + 1];
#pragma unroll
        for (int mt = 0; mt < 2; mt++) {
            int row = m0 + (wm * 2 + mt) * 16 + (lane >> 2);
            float2 v0 = make_float2(acc[mt][nt][0] + bx, acc[mt][nt][1] + by);
            float2 v1 = make_float2(acc[mt][nt][2] + bx, acc[mt][nt][3] + by);
            *(float2*)&g_G0[(size_t)row * GATES + col] = v0;
            *(float2*)&g_G0[(size_t)(row + 8) * GATES + col] = v1;
        }
    }
}

// -------- phase A: fused h1@Whh1 + h0@Whh0 ; B from SMEM ----------------------
// 2 chains per output (iteration parity) for HMMA pipelining.
__device__ __forceinline__ void run_phaseA(
    const uint* __restrict__ a1_base, const uint* __restrict__ a0_base,
    const uint2* ws2, const uint2* ws0,
    int mi, int lane, int rot, float d1[2][4], float d0[2][4])
{
    const uint4* a1 = (const uint4*)a1_base + (size_t)mi * 2048 + lane;
    const uint4* a0 = (const uint4*)a0_base + (size_t)mi * 2048 + lane;
#pragma unroll 4
    for (int i = 0; i < 64; i++) {
        int off = ((i + rot) & 63) * 32;
        uint4 A1 = a1[off];
        uint2 B2 = ws2[off + lane];
        uint4 A0 = a0[off];
        uint2 B0 = ws0[off + lane];
        mmah(d1[i & 1], A1, B2.x, B2.y);
        mmah(d0[i & 1], A0, B0.x, B0.y);
    }
}

// -------- phase B: h0_new@Wih1 ; B from SMEM ----------------------------------
__device__ __forceinline__ void run_phaseB(
    const uint* __restrict__ a_base, const uint2* ws1,
    int mi, int lane, int rot, float d[2][4])
{
    const uint4* a = (const uint4*)a_base + (size_t)mi * 2048 + lane;
#pragma unroll 4
    for (int i = 0; i < 64; i++) {
        int off = ((i + rot) & 63) * 32;
        uint4 A = a[off];
        uint2 B = ws1[off + lane];
        mmah(d[i & 1], A, B.x, B.y);
    }
}

// ---------------- persistent recurrent kernel ---------------------------------
__global__ void __launch_bounds__(NTH) lstm_persistent(
    const float* __restrict__ bi1, const float* __restrict__ bh1,
    float* __restrict__ out)
{
    extern __shared__ uint2 wsm[];         // 24576 uint2 = 192KB weight slab
    __shared__ float ds[64 * 33];          // D routing tile, pad 33 -> conflict-free

    const int tid  = threadIdx.x;
    const int lane = tid & 31;
    const int warp = tid >> 5;
    const int mi   = warp & 3;             // 16-row tile
    const int ni   = warp >> 2;            // 8-col tile
    const int cta  = blockIdx.x;
    const int u_start = cta * UPC;
    const int rot  = cta & 63;             // per-CTA k-rotation: de-camp L2 slices

    // epilogue thread mapping: tid<256 -> (b, s): units 2s, 2s+1 of this CTA
    const int eb = tid & 63;
    const int es = tid >> 6;               // 0..3 when tid<256

    // load the whole weight slab into SMEM once (192KB, coalesced)
    {
        const uint2* src = g_wf + (size_t)cta * WSM_U2;
        for (int i = tid; i < WSM_U2; i += NTH) wsm[i] = src[i];
    }

    // zero parity-0 h fragments
    {
        int i0 = cta * NTH + tid;          // 0..65535
        if (i0 < 32768) { g_h0f[0][i0] = 0u; g_h1f[0][i0] = 0u; }
    }
    float c0r[2] = {0.f, 0.f}, c1r[2] = {0.f, 0.f};
    float b1r[8];
    if (tid < 256) {
#pragma unroll
        for (int g = 0; g < 4; g++)
#pragma unroll
            for (int j = 0; j < 2; j++)
                b1r[g * 2 + j] = bi1[g * HID + u_start + 2 * es + j]
                               + bh1[g * HID + u_start + 2 * es + j];
    }
    // fragment store slot for this epilogue thread
    const int f_kstep = cta >> 1, f_khalf = cta & 1;
    const int f_row = eb & 15, f_mt = eb >> 4;
    const int f_reg = ((f_row >= 8) ? 1 : 0) + (f_khalf ? 2 : 0);
    const int f_idx = (((f_mt * 64 + f_kstep) * 32 + (f_row & 7) * 4) + es) * 4 + f_reg;

    unsigned my_epoch = 0;
    grid_sync(my_epoch);                   // also orders the SMEM weight load

    // per-warp SMEM weight bases (uint2 units): [mat][ni][ks][lane]
    const uint2* ws0 = wsm + ((size_t)(0 * 4 + ni)) * 2048;   // Whh0
    const uint2* ws1 = wsm + ((size_t)(1 * 4 + ni)) * 2048;   // Wih1
    const uint2* ws2 = wsm + ((size_t)(2 * 4 + ni)) * 2048;   // Whh1

    const int r0  = 16 * mi + (lane >> 2);
    const int cc0 = 8 * ni + (lane & 3) * 2;

    for (int t = 0; t < T_STEPS; t++) {
        const int par = t & 1, nxt = par ^ 1;

        // L2-prefetch this step's G0 slice
        if (tid < 64) {
            const float* gp = g_G0 + ((size_t)t * BATCH + tid) * GATES + u_start;
            prefetchL2(gp);
            prefetchL2(gp + HID);
            prefetchL2(gp + 2 * HID);
            prefetchL2(gp + 3 * HID);
        }

        // ===== phase A: h1_prev@Whh1 (carry) + h0_prev@Whh0 (layer 0) =====
        float d1[2][4] = {{0.f,0.f,0.f,0.f},{0.f,0.f,0.f,0.f}};
        {
            float d0[2][4] = {{0.f,0.f,0.f,0.f},{0.f,0.f,0.f,0.f}};
            run_phaseA(g_h1f[par], g_h0f[par], ws2, ws0, mi, lane, rot, d1, d0);
            ds[r0 * 33 + cc0]           = d0[0][0] + d0[1][0];
            ds[r0 * 33 + cc0 + 1]       = d0[0][1] + d0[1][1];
            ds[(r0 + 8) * 33 + cc0]     = d0[0][2] + d0[1][2];
            ds[(r0 + 8) * 33 + cc0 + 1] = d0[0][3] + d0[1][3];
        }
        __syncthreads();
        if (tid < 256) {                    // layer-0 epilogue: thread = (b, unit pair)
            const float* gp = g_G0 + ((size_t)t * BATCH + eb) * GATES + u_start + 2 * es;
            float hf[2];
#pragma unroll
            for (int j = 0; j < 2; j++) {
                int u = 2 * es + j;
                float gi = ds[eb * 33 + u * 4 + 0] + gp[j];
                float gf = ds[eb * 33 + u * 4 + 1] + gp[HID + j];
                float gg = ds[eb * 33 + u * 4 + 2] + gp[2 * HID + j];
                float go = ds[eb * 33 + u * 4 + 3] + gp[3 * HID + j];
                float c = sigmoidf_(gf) * c0r[j] + sigmoidf_(gi) * tanhf(gg);
                c0r[j] = c;
                hf[j] = sigmoidf_(go) * tanhf(c);
            }
            g_h0f[nxt][f_idx] = pack_h2(__float2half_rn(hf[0]), __float2half_rn(hf[1]));
            if (t == T_STEPS - 1) {
                float* so = out + (size_t)T_STEPS * BATCH * HID;
                int u0 = u_start + 2 * es;
                *(float2*)&so[eb * HID + u0]         = make_float2(hf[0], hf[1]);
                *(float2*)&so[65536 + eb * HID + u0] = make_float2(c0r[0], c0r[1]);
            }
        }
        grid_sync(my_epoch);

        // ===== phase B: += h0_new@Wih1 (layer-1 remainder) =====
        run_phaseB(g_h0f[nxt], ws1, mi, lane, rot, d1);
        ds[r0 * 33 + cc0]           = d1[0][0] + d1[1][0];
        ds[r0 * 33 + cc0 + 1]       = d1[0][1] + d1[1][1];
        ds[(r0 + 8) * 33 + cc0]     = d1[0][2] + d1[1][2];
        ds[(r0 + 8) * 33 + cc0 + 1] = d1[0][3] + d1[1][3];
        __syncthreads();
        if (tid < 256) {                    // layer-1 epilogue
            float hf[2];
#pragma unroll
            for (int j = 0; j < 2; j++) {
                int u = 2 * es + j;
                float gi = ds[eb * 33 + u * 4 + 0] + b1r[j];
                float gf = ds[eb * 33 + u * 4 + 1] + b1r[2 + j];
                float gg = ds[eb * 33 + u * 4 + 2] + b1r[4 + j];
                float go = ds[eb * 33 + u * 4 + 3] + b1r[6 + j];
                float c = sigmoidf_(gf) * c1r[j] + sigmoidf_(gi) * tanhf(gg);
                c1r[j] = c;
                hf[j] = sigmoidf_(go) * tanhf(c);
            }
            g_h1f[nxt][f_idx] = pack_h2(__float2half_rn(hf[0]), __float2half_rn(hf[1]));
            int u0 = u_start + 2 * es;
            *(float2*)&out[((size_t)t * BATCH + eb) * HID + u0] = make_float2(hf[0], hf[1]);
            if (t == T_STEPS - 1) {
                float* so = out + (size_t)T_STEPS * BATCH * HID;
                *(float2*)&so[131072 + eb * HID + u0] = make_float2(hf[0], hf[1]);
                *(float2*)&so[196608 + eb * HID + u0] = make_float2(c1r[0], c1r[1]);
            }
        }
        grid_sync(my_epoch);
    }

    // ---- reset barrier vars for deterministic graph replay ----
    __threadfence();
    __syncthreads();
    if (tid == 0) {
        if (atomicAdd(&g_done_cnt, 1u) == (unsigned)NB - 1u) {
            g_done_cnt = 0u;
            g_bar_cnt  = 0u;
            __threadfence();
            g_bar_epoch = 0u;
        }
    }
}

// ---------------- launch ------------------------------------------------------
extern "C" void kernel_launch(void* const* d_in, const int* in_sizes, int n_in,
                              void* d_out, int out_size) {
    const float* X     = (const float*)d_in[0];
    const float* Wih0  = (const float*)d_in[1];
    const float* Whh0  = (const float*)d_in[2];
    const float* bih0  = (const float*)d_in[3];
    const float* bhh0  = (const float*)d_in[4];
    const float* Wih1  = (const float*)d_in[5];
    const float* Whh1  = (const float*)d_in[6];
    const float* bih1  = (const float*)d_in[7];
    const float* bhh1  = (const float*)d_in[8];
    float* out = (float*)d_out;

    prep_w<<<12288, 256>>>(Whh0, Wih1, Whh1);

    dim3 ggrid(GATES / 128, (T_STEPS * BATCH) / 128);   // 32 x 256 blocks
    gemm_g0_bf16<<<ggrid, 512>>>(X, Wih0, bih0, bhh0);

    const int wsm_bytes = WSM_U2 * (int)sizeof(uint2);  // 196608
    cudaFuncSetAttribute(lstm_persistent,
                         cudaFuncAttributeMaxDynamicSharedMemorySize, wsm_bytes);
    lstm_persistent<<<NB, NTH, wsm_bytes>>>(bih1, bhh1, out);
}

// round 17
// speedup vs baseline: 2.5624x; 1.3175x over previous
#include <cuda_runtime.h>
#include <cuda_bf16.h>
#include <cuda_fp16.h>
#include <cstdint>

typedef unsigned long long ull;
typedef unsigned int uint;

#define T_STEPS 512
#define BATCH   64
#define DIN     512
#define HID     1024
#define GATES   4096
#define NB      128          // persistent grid: 128 CTAs x 8 units = 1024
#define NTH     512          // 16 warps: mi = w&3 (16-row), ni = w>>2 (8-col)
#define UPC     8

// dynamic SMEM: weight slab, 3 mats x 4 ni x 64 ks x 32 lanes x uint2 = 196608 B
#define WSM_U2  (3 * 4 * 64 * 32)

// ---------------- scratch -----------------------------------------------------
__device__ float g_G0[(size_t)T_STEPS * BATCH * GATES];       // X@Wih0^T + biases
// weights, SINGLE fp16 plane, per-lane B-fragment order:
// [cta][mat 3][ni 4][kstep 64][lane 32] ; uint2 = {b0, b1}
__device__ uint2 g_wf[(size_t)NB * WSM_U2];
// hidden states, SINGLE fp16 plane, A-fragment order:
// [parity][((mt*64+ks)*32+lane)*4+reg]
__device__ uint g_h0f[2][32768];
__device__ uint g_h1f[2][32768];
__device__ unsigned g_bar_cnt;
__device__ volatile unsigned g_bar_epoch;
__device__ unsigned g_done_cnt;

// ---------------- helpers -----------------------------------------------------
__device__ __forceinline__ float sigmoidf_(float x) { return 1.0f / (1.0f + expf(-x)); }

// fp16 mma m16n8k16
__device__ __forceinline__ void mmah(float d[4], uint4 A, uint b0, uint b1) {
    asm volatile("mma.sync.aligned.m16n8k16.row.col.f32.f16.f16.f32 "
        "{%0,%1,%2,%3}, {%4,%5,%6,%7}, {%8,%9}, {%0,%1,%2,%3};"
        : "+f"(d[0]), "+f"(d[1]), "+f"(d[2]), "+f"(d[3])
        : "r"(A.x), "r"(A.y), "r"(A.z), "r"(A.w), "r"(b0), "r"(b1));
}
// bf16 mma (gemm_g0 only)
__device__ __forceinline__ void mma16816(float d[4], uint a0, uint a1, uint a2, uint a3,
                                         uint b0, uint b1) {
    asm volatile("mma.sync.aligned.m16n8k16.row.col.f32.bf16.bf16.f32 "
        "{%0,%1,%2,%3}, {%4,%5,%6,%7}, {%8,%9}, {%0,%1,%2,%3};"
        : "+f"(d[0]), "+f"(d[1]), "+f"(d[2]), "+f"(d[3])
        : "r"(a0), "r"(a1), "r"(a2), "r"(a3), "r"(b0), "r"(b1));
}

__device__ __forceinline__ void prefetchL2(const void* p) {
    asm volatile("prefetch.global.L2 [%0];" :: "l"(p));
}

__device__ __forceinline__ void grid_sync(unsigned &my_epoch) {
    __threadfence();
    __syncthreads();
    if (threadIdx.x == 0) {
        my_epoch++;
        if (atomicAdd(&g_bar_cnt, 1u) == (unsigned)NB - 1u) {
            g_bar_cnt = 0u;
            __threadfence();
            g_bar_epoch = my_epoch;
        } else {
            while (g_bar_epoch < my_epoch) { }
            __threadfence();
        }
    }
    __syncthreads();
}

// bf16 pack/split (gemm_g0)
__device__ __forceinline__ uint pack_bf2(__nv_bfloat16 lo16, __nv_bfloat16 hi16) {
    return (uint)__bfloat16_as_ushort(lo16) | ((uint)__bfloat16_as_ushort(hi16) << 16);
}
__device__ __forceinline__ void split2(float x, float y, uint &hi, uint &lo) {
    __nv_bfloat16 xh = __float2bfloat16(x), yh = __float2bfloat16(y);
    hi = pack_bf2(xh, yh);
    lo = pack_bf2(__float2bfloat16(x - __bfloat162float(xh)),
                  __float2bfloat16(y - __bfloat162float(yh)));
}
// fp16 pack
__device__ __forceinline__ uint pack_h2(__half a, __half b) {
    return (uint)__half_as_ushort(a) | ((uint)__half_as_ushort(b) << 16);
}

// ---------------- prep: weights -> B-fragment order, single fp16 --------------
__global__ void __launch_bounds__(256) prep_w(
    const float* __restrict__ Whh0, const float* __restrict__ Wih1,
    const float* __restrict__ Whh1)
{
    uint idx = blockIdx.x * 256u + threadIdx.x;
    uint lane = idx & 31u;
    uint ks   = (idx >> 5) & 63u;
    uint ni   = (idx >> 11) & 3u;
    uint cm   = idx >> 13;
    uint mat  = cm % 3u, cta = cm / 3u;

    const float* W = (mat == 0) ? Whh0 : (mat == 1) ? Wih1 : Whh1;
    uint n  = ni * 8u + (lane >> 2);       // col within CTA's 32: n = lu*4 + g
    uint lu = n >> 2, g = n & 3u;
    const float* row = W + (size_t)(g * HID + cta * UPC + lu) * HID;
    uint k0 = ks * 16u + (lane & 3u) * 2u;

    uint2 v;
    v.x = pack_h2(__float2half_rn(row[k0]),     __float2half_rn(row[k0 + 1]));
    v.y = pack_h2(__float2half_rn(row[k0 + 8]), __float2half_rn(row[k0 + 9]));
    g_wf[(((size_t)(cta * 3 + mat) * 4 + ni) * 64 + ks) * 32 + lane] = v;
}

// ---------------- tensorized G0 GEMM (round-12, proven) -----------------------
__global__ void __launch_bounds__(512) gemm_g0_bf16(
    const float* __restrict__ X, const float* __restrict__ W,
    const float* __restrict__ bi, const float* __restrict__ bh)
{
    __shared__ uint As[2][2][8][32][4];
    __shared__ uint Bs[2][2][16][32][2];

    const int tid  = threadIdx.x;
    const int lane = tid & 31;
    const int warp = tid >> 5;
    const int wm   = warp >> 2;
    const int wn   = warp & 3;
    const int m0 = blockIdx.y * 128, n0 = blockIdx.x * 128;

    const int lrow = tid >> 2;
    const int c0   = (tid & 3) * 4;
    const int j0   = c0 >> 1;
    const int a_mt  = lrow >> 4, a_rr = lrow & 15;
    const int a_reg = (a_rr >= 8 ? 1 : 0) + (j0 >= 4 ? 2 : 0);
    const int a_ln  = (a_rr & 7) * 4 + (j0 & 3);
    const int b_nt  = lrow >> 3, b_nn = lrow & 7;
    const int b_reg = (j0 >= 4 ? 1 : 0);
    const int b_ln  = b_nn * 4 + (j0 & 3);

    const float* xrow = X + (size_t)(m0 + lrow) * DIN;
    const float* wrow = W + (size_t)(n0 + lrow) * DIN;

    float acc[2][4][4];
#pragma unroll
    for (int mt = 0; mt < 2; mt++)
#pragma unroll
        for (int nt = 0; nt < 4; nt++)
#pragma unroll
            for (int r = 0; r < 4; r++) acc[mt][nt][r] = 0.f;

    {
        float4 xv = *(const float4*)&xrow[c0];
        uint h0, l0, h1, l1;
        split2(xv.x, xv.y, h0, l0);
        split2(xv.z, xv.w, h1, l1);
        As[0][0][a_mt][a_ln][a_reg] = h0;  As[0][0][a_mt][a_ln + 1][a_reg] = h1;
        As[0][1][a_mt][a_ln][a_reg] = l0;  As[0][1][a_mt][a_ln + 1][a_reg] = l1;
        float4 wv = *(const float4*)&wrow[c0];
        split2(wv.x, wv.y, h0, l0);
        split2(wv.z, wv.w, h1, l1);
        Bs[0][0][b_nt][b_ln][b_reg] = h0;  Bs[0][0][b_nt][b_ln + 1][b_reg] = h1;
        Bs[0][1][b_nt][b_ln][b_reg] = l0;  Bs[0][1][b_nt][b_ln + 1][b_reg] = l1;
    }
    __syncthreads();

    int buf = 0;
#pragma unroll 1
    for (int ks = 0; ks < 32; ks++) {
        if (ks + 1 < 32) {
            int kk = (ks + 1) * 16 + c0;
            float4 xv = *(const float4*)&xrow[kk];
            uint h0, l0, h1, l1;
            split2(xv.x, xv.y, h0, l0);
            split2(xv.z, xv.w, h1, l1);
            As[buf ^ 1][0][a_mt][a_ln][a_reg] = h0;  As[buf ^ 1][0][a_mt][a_ln + 1][a_reg] = h1;
            As[buf ^ 1][1][a_mt][a_ln][a_reg] = l0;  As[buf ^ 1][1][a_mt][a_ln + 1][a_reg] = l1;
            float4 wv = *(const float4*)&wrow[kk];
            split2(wv.x, wv.y, h0, l0);
            split2(wv.z, wv.w, h1, l1);
            Bs[buf ^ 1][0][b_nt][b_ln][b_reg] = h0;  Bs[buf ^ 1][0][b_nt][b_ln + 1][b_reg] = h1;
            Bs[buf ^ 1][1][b_nt][b_ln][b_reg] = l0;  Bs[buf ^ 1][1][b_nt][b_ln + 1][b_reg] = l1;
        }
#pragma unroll
        for (int mt = 0; mt < 2; mt++) {
            uint4 Ah = *(uint4*)&As[buf][0][wm * 2 + mt][lane][0];
            uint4 Al = *(uint4*)&As[buf][1][wm * 2 + mt][lane][0];
#pragma unroll
            for (int nt = 0; nt < 4; nt++) {
                uint2 Bh = *(uint2*)&Bs[buf][0][wn * 4 + nt][lane][0];
                uint2 Bl = *(uint2*)&Bs[buf][1][wn * 4 + nt][lane][0];
                mma16816(acc[mt][nt], Ah.x, Ah.y, Ah.z, Ah.w, Bh.x, Bh.y);
                mma16816(acc[mt][nt], Al.x, Al.y, Al.z, Al.w, Bh.x, Bh.y);
                mma16816(acc[mt][nt], Ah.x, Ah.y, Ah.z, Ah.w, Bl.x, Bl.y);
            }
        }
        __syncthreads();
        buf ^= 1;
    }

#pragma unroll
    for (int nt = 0; nt < 4; nt++) {
        int col = n0 + (wn * 4 + nt) * 8 + 2 * (lane & 3);
        float bx = bi[col] + bh[col];
        float by = bi[col + 1] + bh[col + 1];
#pragma unroll
        for (int mt = 0; mt < 2; mt++) {
            int row = m0 + (wm * 2 + mt) * 16 + (lane >> 2);
            float2 v0 = make_float2(acc[mt][nt][0] + bx, acc[mt][nt][1] + by);
            float2 v1 = make_float2(acc[mt][nt][2] + bx, acc[mt][nt][3] + by);
            *(float2*)&g_G0[(size_t)row * GATES + col] = v0;
            *(float2*)&g_G0[(size_t)(row + 8) * GATES + col] = v1;
        }
    }
}

// -------- fused k-loop: layer0 + lagged layer1, ONE pass, B from SMEM ---------
// d0  = h0[p] @ Whh0      (layer0, 2 parity chains)
// d1a = h0[p] @ Wih1      (layer1 part, shares A0 load!)
// d1b = h1[p] @ Whh1      (layer1 part)
template<bool L0, bool L1>
__device__ __forceinline__ void kloop(
    const uint* __restrict__ a0_base, const uint* __restrict__ a1_base,
    const uint2* ws0, const uint2* ws1, const uint2* ws2,
    int mi, int lane, int rot,
    float d0[2][4], float d1a[2][4], float d1b[2][4])
{
    const uint4* a0 = (const uint4*)a0_base + (size_t)mi * 2048 + lane;
    const uint4* a1 = (const uint4*)a1_base + (size_t)mi * 2048 + lane;
#pragma unroll 4
    for (int i = 0; i < 64; i++) {
        int off = ((i + rot) & 63) * 32;
        uint4 A0 = a0[off];
        if (L1) {
            uint4 A1 = a1[off];
            uint2 B1 = ws1[off + lane];
            uint2 B2 = ws2[off + lane];
            mmah(d1a[i & 1], A0, B1.x, B1.y);
            mmah(d1b[i & 1], A1, B2.x, B2.y);
        }
        if (L0) {
            uint2 B0 = ws0[off + lane];
            mmah(d0[i & 1], A0, B0.x, B0.y);
        }
    }
}

// ---------------- persistent recurrent kernel ---------------------------------
__global__ void __launch_bounds__(NTH) lstm_persistent(
    const float* __restrict__ bi1, const float* __restrict__ bh1,
    float* __restrict__ out)
{
    extern __shared__ uint2 wsm[];         // 24576 uint2 = 192KB weight slab
    __shared__ float ds0[64 * 33];         // layer0 D tile
    __shared__ float ds1[64 * 33];         // layer1 D tile

    const int tid  = threadIdx.x;
    const int lane = tid & 31;
    const int warp = tid >> 5;
    const int mi   = warp & 3;             // 16-row tile
    const int ni   = warp >> 2;            // 8-col tile
    const int cta  = blockIdx.x;
    const int u_start = cta * UPC;
    const int rot  = cta & 63;             // per-CTA k-rotation: de-camp L2 slices

    // epilogue mapping: half 0 (tid<256) = layer0, half 1 (tid>=256) = layer1
    const int eb   = tid & 63;
    const int es   = (tid >> 6) & 3;
    const int half = tid >> 8;

    // load the whole weight slab into SMEM once (192KB, coalesced)
    {
        const uint2* src = g_wf + (size_t)cta * WSM_U2;
        for (int i = tid; i < WSM_U2; i += NTH) wsm[i] = src[i];
    }

    // zero h0f parity 0 and h1f parity 1 (the two buffers read before written)
    {
        int i0 = cta * NTH + tid;          // 0..65535
        if (i0 < 32768) { g_h0f[0][i0] = 0u; g_h1f[1][i0] = 0u; }
    }
    float cr[2] = {0.f, 0.f};              // c0 (half 0) or c1 (half 1)
    float b1r[8];
    if (half == 1) {
#pragma unroll
        for (int g = 0; g < 4; g++)
#pragma unroll
            for (int j = 0; j < 2; j++)
                b1r[g * 2 + j] = bi1[g * HID + u_start + 2 * es + j]
                               + bh1[g * HID + u_start + 2 * es + j];
    }
    // fragment store slot for this epilogue thread
    const int f_kstep = cta >> 1, f_khalf = cta & 1;
    const int f_row = eb & 15, f_mt = eb >> 4;
    const int f_reg = ((f_row >= 8) ? 1 : 0) + (f_khalf ? 2 : 0);
    const int f_idx = (((f_mt * 64 + f_kstep) * 32 + (f_row & 7) * 4) + es) * 4 + f_reg;

    unsigned my_epoch = 0;
    grid_sync(my_epoch);                   // also orders the SMEM weight load

    const uint2* ws0 = wsm + ((size_t)(0 * 4 + ni)) * 2048;   // Whh0
    const uint2* ws1 = wsm + ((size_t)(1 * 4 + ni)) * 2048;   // Wih1
    const uint2* ws2 = wsm + ((size_t)(2 * 4 + ni)) * 2048;   // Whh1

    const int r0  = 16 * mi + (lane >> 2);
    const int cc0 = 8 * ni + (lane & 3) * 2;

    // 513 phases: phase ph = layer0 step ph (ph<512) + layer1 step ph-1 (ph>=1)
    for (int ph = 0; ph <= T_STEPS; ph++) {
        const int p = ph & 1, q = p ^ 1;
        const bool L0 = (ph < T_STEPS), L1 = (ph >= 1);

        if (L0 && tid < 64) {              // L2-prefetch G0 slice for step ph
            const float* gp = g_G0 + ((size_t)ph * BATCH + tid) * GATES + u_start;
            prefetchL2(gp);
            prefetchL2(gp + HID);
            prefetchL2(gp + 2 * HID);
            prefetchL2(gp + 3 * HID);
        }

        float d0[2][4]  = {{0.f,0.f,0.f,0.f},{0.f,0.f,0.f,0.f}};
        float d1a[2][4] = {{0.f,0.f,0.f,0.f},{0.f,0.f,0.f,0.f}};
        float d1b[2][4] = {{0.f,0.f,0.f,0.f},{0.f,0.f,0.f,0.f}};

        if (L0 && L1)
            kloop<true, true>(g_h0f[p], g_h1f[p], ws0, ws1, ws2, mi, lane, rot, d0, d1a, d1b);
        else if (L0)
            kloop<true, false>(g_h0f[p], g_h1f[p], ws0, ws1, ws2, mi, lane, rot, d0, d1a, d1b);
        else
            kloop<false, true>(g_h0f[p], g_h1f[p], ws0, ws1, ws2, mi, lane, rot, d0, d1a, d1b);

        if (L0) {
            ds0[r0 * 33 + cc0]           = d0[0][0] + d0[1][0];
            ds0[r0 * 33 + cc0 + 1]       = d0[0][1] + d0[1][1];
            ds0[(r0 + 8) * 33 + cc0]     = d0[0][2] + d0[1][2];
            ds0[(r0 + 8) * 33 + cc0 + 1] = d0[0][3] + d0[1][3];
        }
        if (L1) {
            ds1[r0 * 33 + cc0]           = d1a[0][0] + d1a[1][0] + d1b[0][0] + d1b[1][0];
            ds1[r0 * 33 + cc0 + 1]       = d1a[0][1] + d1a[1][1] + d1b[0][1] + d1b[1][1];
            ds1[(r0 + 8) * 33 + cc0]     = d1a[0][2] + d1a[1][2] + d1b[0][2] + d1b[1][2];
            ds1[(r0 + 8) * 33 + cc0 + 1] = d1a[0][3] + d1a[1][3] + d1b[0][3] + d1b[1][3];
        }
        __syncthreads();

        if (half == 0) {
            if (L0) {                       // layer0 epilogue, step t = ph
                const float* gp = g_G0 + ((size_t)ph * BATCH + eb) * GATES + u_start + 2 * es;
                float hf[2];
#pragma unroll
                for (int j = 0; j < 2; j++) {
                    int u = 2 * es + j;
                    float gi = ds0[eb * 33 + u * 4 + 0] + gp[j];
                    float gf = ds0[eb * 33 + u * 4 + 1] + gp[HID + j];
                    float gg = ds0[eb * 33 + u * 4 + 2] + gp[2 * HID + j];
                    float go = ds0[eb * 33 + u * 4 + 3] + gp[3 * HID + j];
                    float c = sigmoidf_(gf) * cr[j] + sigmoidf_(gi) * tanhf(gg);
                    cr[j] = c;
                    hf[j] = sigmoidf_(go) * tanhf(c);
                }
                g_h0f[q][f_idx] = pack_h2(__float2half_rn(hf[0]), __float2half_rn(hf[1]));
                if (ph == T_STEPS - 1) {
                    float* so = out + (size_t)T_STEPS * BATCH * HID;
                    int u0 = u_start + 2 * es;
                    *(float2*)&so[eb * HID + u0]         = make_float2(hf[0], hf[1]);
                    *(float2*)&so[65536 + eb * HID + u0] = make_float2(cr[0], cr[1]);
                }
            }
        } else {
            if (L1) {                       // layer1 epilogue, step t = ph-1
                const int t1 = ph - 1;
                float hf[2];
#pragma unroll
                for (int j = 0; j < 2; j++) {
                    int u = 2 * es + j;
                    float gi = ds1[eb * 33 + u * 4 + 0] + b1r[j];
                    float gf = ds1[eb * 33 + u * 4 + 1] + b1r[2 + j];
                    float gg = ds1[eb * 33 + u * 4 + 2] + b1r[4 + j];
                    float go = ds1[eb * 33 + u * 4 + 3] + b1r[6 + j];
                    float c = sigmoidf_(gf) * cr[j] + sigmoidf_(gi) * tanhf(gg);
                    cr[j] = c;
                    hf[j] = sigmoidf_(go) * tanhf(c);
                }
                g_h1f[q][f_idx] = pack_h2(__float2half_rn(hf[0]), __float2half_rn(hf[1]));
                int u0 = u_start + 2 * es;
                *(float2*)&out[((size_t)t1 * BATCH + eb) * HID + u0] = make_float2(hf[0], hf[1]);
                if (ph == T_STEPS) {
                    float* so = out + (size_t)T_STEPS * BATCH * HID;
                    *(float2*)&so[131072 + eb * HID + u0] = make_float2(hf[0], hf[1]);
                    *(float2*)&so[196608 + eb * HID + u0] = make_float2(cr[0], cr[1]);
                }
            }
        }
        grid_sync(my_epoch);
    }

    // ---- reset barrier vars for deterministic graph replay ----
    __threadfence();
    __syncthreads();
    if (tid == 0) {
        if (atomicAdd(&g_done_cnt, 1u) == (unsigned)NB - 1u) {
            g_done_cnt = 0u;
            g_bar_cnt  = 0u;
            __threadfence();
            g_bar_epoch = 0u;
        }
    }
}

// ---------------- launch ------------------------------------------------------
extern "C" void kernel_launch(void* const* d_in, const int* in_sizes, int n_in,
                              void* d_out, int out_size) {
    const float* X     = (const float*)d_in[0];
    const float* Wih0  = (const float*)d_in[1];
    const float* Whh0  = (const float*)d_in[2];
    const float* bih0  = (const float*)d_in[3];
    const float* bhh0  = (const float*)d_in[4];
    const float* Wih1  = (const float*)d_in[5];
    const float* Whh1  = (const float*)d_in[6];
    const float* bih1  = (const float*)d_in[7];
    const float* bhh1  = (const float*)d_in[8];
    float* out = (float*)d_out;

    prep_w<<<12288, 256>>>(Whh0, Wih1, Whh1);

    dim3 ggrid(GATES / 128, (T_STEPS * BATCH) / 128);   // 32 x 256 blocks
    gemm_g0_bf16<<<ggrid, 512>>>(X, Wih0, bih0, bhh0);

    const int wsm_bytes = WSM_U2 * (int)sizeof(uint2);  // 196608
    cudaFuncSetAttribute(lstm_persistent,
                         cudaFuncAttributeMaxDynamicSharedMemorySize, wsm_bytes);
    lstm_persistent<<<NB, NTH, wsm_bytes>>>(bih1, bhh1, out);
}